// round 14
// baseline (speedup 1.0000x reference)
#include <cuda_runtime.h>
#include <cuda_bf16.h>
#include <cstdint>
#include <math.h>

#define S_LEN 2048
#define E_DIM 1024
#define NH    16
#define DH    64

// ---------------------------------------------------------------------------
// Scratch (__device__ globals; allocation-free rule)
// ---------------------------------------------------------------------------
__device__ __align__(16) __nv_bfloat16 g_qh[NH * S_LEN * DH];
__device__ __align__(16) __nv_bfloat16 g_ql[NH * S_LEN * DH];
__device__ __align__(16) __nv_bfloat16 g_kh[NH * S_LEN * DH];
__device__ __align__(16) __nv_bfloat16 g_kl[NH * S_LEN * DH];
__device__ __align__(16) __nv_bfloat16 g_vh[NH * S_LEN * DH];
__device__ __align__(16) __nv_bfloat16 g_vl[NH * S_LEN * DH];

__device__ __align__(16) __nv_bfloat16 g_xh[S_LEN * E_DIM];
__device__ __align__(16) __nv_bfloat16 g_xl[S_LEN * E_DIM];
__device__ __align__(16) __nv_bfloat16 g_wth[3 * E_DIM * E_DIM];
__device__ __align__(16) __nv_bfloat16 g_wtl[3 * E_DIM * E_DIM];
__device__ __align__(16) __nv_bfloat16 g_woth[E_DIM * E_DIM];
__device__ __align__(16) __nv_bfloat16 g_wotl[E_DIM * E_DIM];
__device__ __align__(16) __nv_bfloat16 g_aoh[S_LEN * E_DIM];
__device__ __align__(16) __nv_bfloat16 g_aol[S_LEN * E_DIM];

// split-KV partials
__device__ __align__(16) float g_opart[2 * NH * S_LEN * DH];
__device__ __align__(16) float g_mpart[2 * NH * S_LEN];
__device__ __align__(16) float g_lpart[2 * NH * S_LEN];

// ---------------------------------------------------------------------------
// Baseline-PTX helpers
// ---------------------------------------------------------------------------
__device__ __forceinline__ uint32_t smem_to_u32(const void* p) {
    uint32_t a;
    asm("{ .reg .u64 t; cvta.to.shared.u64 t, %1; cvt.u32.u64 %0, t; }"
        : "=r"(a) : "l"(p));
    return a;
}

__device__ __forceinline__ void ldsm4(uint32_t* r, uint32_t addr) {
    asm volatile("ldmatrix.sync.aligned.m8n8.x4.shared.b16 {%0,%1,%2,%3}, [%4];"
        : "=r"(r[0]), "=r"(r[1]), "=r"(r[2]), "=r"(r[3]) : "r"(addr));
}
__device__ __forceinline__ void ldsm4t(uint32_t* r, uint32_t addr) {
    asm volatile("ldmatrix.sync.aligned.m8n8.x4.trans.shared.b16 {%0,%1,%2,%3}, [%4];"
        : "=r"(r[0]), "=r"(r[1]), "=r"(r[2]), "=r"(r[3]) : "r"(addr));
}

__device__ __forceinline__ void mma16816(float* c, const uint32_t* a, const uint32_t* b) {
    asm volatile(
        "mma.sync.aligned.m16n8k16.row.col.f32.bf16.bf16.f32 "
        "{%0,%1,%2,%3}, {%4,%5,%6,%7}, {%8,%9}, {%0,%1,%2,%3};"
        : "+f"(c[0]), "+f"(c[1]), "+f"(c[2]), "+f"(c[3])
        : "r"(a[0]), "r"(a[1]), "r"(a[2]), "r"(a[3]), "r"(b[0]), "r"(b[1]));
}

__device__ __forceinline__ void cpasync16(uint32_t saddr, const void* gaddr) {
    asm volatile("cp.async.cg.shared.global [%0], [%1], 16;"
        :: "r"(saddr), "l"(gaddr) : "memory");
}
#define CP_COMMIT() asm volatile("cp.async.commit_group;" ::: "memory")
#define CP_WAIT(n)  asm volatile("cp.async.wait_group %0;" :: "n"(n) : "memory")

__device__ __forceinline__ void split1(float v, __nv_bfloat16& h, __nv_bfloat16& l) {
    h = __float2bfloat16(v);
    l = __float2bfloat16(v - __bfloat162float(h));
}
__device__ __forceinline__ void packsplit2(float a, float b, uint32_t& hi, uint32_t& lo) {
    __nv_bfloat162 h, l;
    h.x = __float2bfloat16(a); h.y = __float2bfloat16(b);
    l.x = __float2bfloat16(a - __bfloat162float(h.x));
    l.y = __float2bfloat16(b - __bfloat162float(h.y));
    hi = *(uint32_t*)&h; lo = *(uint32_t*)&l;
}
__device__ __forceinline__ void splitstore2(float a, float b,
                                            __nv_bfloat16* ph, __nv_bfloat16* pl) {
    __nv_bfloat162 h, l;
    h.x = __float2bfloat16(a); h.y = __float2bfloat16(b);
    l.x = __float2bfloat16(a - __bfloat162float(h.x));
    l.y = __float2bfloat16(b - __bfloat162float(h.y));
    *(__nv_bfloat162*)ph = h; *(__nv_bfloat162*)pl = l;
}

// swizzled byte offset, 64B rows (4x16B chunks)
__device__ __forceinline__ uint32_t swz(uint32_t row, uint32_t chunk) {
    return row * 64 + ((chunk ^ ((row >> 1) & 3)) << 4);
}
// swizzled byte offset, 128B rows (8x16B chunks)
__device__ __forceinline__ uint32_t swz8(uint32_t row, uint32_t chunk) {
    return row * 128 + ((chunk ^ (row & 7)) << 4);
}

// ---------------------------------------------------------------------------
// Merged prologue: z<3 Wqkv, z==3 Wo, z>=4 x split. grid(16,16,12)
// ---------------------------------------------------------------------------
__global__ __launch_bounds__(256) void prep_kernel(
    const float* __restrict__ x,
    const float* __restrict__ Wq, const float* __restrict__ Wk,
    const float* __restrict__ Wv, const float* __restrict__ Wo)
{
    const int z = blockIdx.z;
    const int tid = threadIdx.x;

    if (z < 3) {
        __shared__ float s[64][65];
        const int h = blockIdx.y, e0 = blockIdx.x * 64;
        const float* W = (z == 0 ? Wq : z == 1 ? Wk : Wv) + (size_t)h * E_DIM * DH;
        #pragma unroll
        for (int i = 0; i < 16; i++) {
            int idx = tid + i * 256;
            int e = idx >> 6, d = idx & 63;
            s[d][e] = W[(size_t)(e0 + e) * DH + d];
        }
        __syncthreads();
        const int nb = z * 1024 + h * 64;
        #pragma unroll
        for (int i = 0; i < 16; i++) {
            int idx = tid + i * 256;
            int d = idx >> 6, e = idx & 63;
            __nv_bfloat16 hh, ll;
            split1(s[d][e], hh, ll);
            g_wth[(size_t)(nb + d) * E_DIM + e0 + e] = hh;
            g_wtl[(size_t)(nb + d) * E_DIM + e0 + e] = ll;
        }
    } else if (z == 3) {
        __shared__ float s[64][65];
        const int f0 = blockIdx.x * 64, e0 = blockIdx.y * 64;
        #pragma unroll
        for (int i = 0; i < 16; i++) {
            int idx = tid + i * 256;
            int fl = idx >> 6, el = idx & 63;
            s[el][fl] = Wo[(size_t)(f0 + fl) * E_DIM + e0 + el];
        }
        __syncthreads();
        #pragma unroll
        for (int i = 0; i < 16; i++) {
            int idx = tid + i * 256;
            int el = idx >> 6, fl = idx & 63;
            __nv_bfloat16 hh, ll;
            split1(s[el][fl], hh, ll);
            g_woth[(size_t)(e0 + el) * E_DIM + f0 + fl] = hh;
            g_wotl[(size_t)(e0 + el) * E_DIM + f0 + fl] = ll;
        }
    } else {
        const int lb = (z - 4) * 256 + blockIdx.y * 16 + blockIdx.x;
        int i = (lb * 256 + tid) * 4;
        float4 v = *(const float4*)(x + i);
        splitstore2(v.x, v.y, g_xh + i, g_xl + i);
        splitstore2(v.z, v.w, g_xh + i + 2, g_xl + i + 2);
    }
}

// ---------------------------------------------------------------------------
// Unified 3-stage cp.async mma.sync bf16-split GEMM, BM=64 / BN=128.
// mode 0: A = x, B = Wqkv_t; grid (32, 24) -> q/k/v bf16 hi/lo (+bias; q*0.125)
// mode 1: A = ao, B = Wot;   grid (32, 8)  -> out fp32 (+bo)
// stage = Ah(4K)+Al(4K)+Bh(8K)+Bl(8K) = 24KB; 3 stages = 72KB; 2 CTAs/SM.
// ---------------------------------------------------------------------------
#define STG64_B 24576
#define GEMM64_SMEM_BYTES (3 * STG64_B)

__global__ __launch_bounds__(256, 2) void gemm64_mma_kernel(
    int mode, const float* __restrict__ bias0, const float* __restrict__ bias1,
    const float* __restrict__ bias2, float* __restrict__ out)
{
    extern __shared__ __nv_bfloat16 gs2[];
    const uint32_t sb = smem_to_u32(gs2);
    const int tid = threadIdx.x;
    const int wid = tid >> 5, lane = tid & 31;
    const int wm = wid >> 2, wn = wid & 3;
    const int m0 = blockIdx.x * 64, n0 = blockIdx.y * 128;

    const __nv_bfloat16* pAh = (mode ? g_aoh : g_xh) + (size_t)m0 * E_DIM;
    const __nv_bfloat16* pAl = (mode ? g_aol : g_xl) + (size_t)m0 * E_DIM;
    const __nv_bfloat16* pBh = (mode ? g_woth : g_wth) + (size_t)n0 * E_DIM;
    const __nv_bfloat16* pBl = (mode ? g_wotl : g_wtl) + (size_t)n0 * E_DIM;

    auto issue = [&](int s, int kc) {
        const int k0 = kc * 32;
        const uint32_t stb = sb + s * STG64_B;
        {   // A tiles: 64 rows x 4 chunks = 256 items
            uint32_t row = tid >> 2, q = tid & 3;
            cpasync16(stb + swz(row, q), pAh + (size_t)row * E_DIM + k0 + q * 8);
            cpasync16(stb + 4096 + swz(row, q), pAl + (size_t)row * E_DIM + k0 + q * 8);
        }
        #pragma unroll
        for (int i = 0; i < 2; i++) {   // B tiles: 128 rows x 4 chunks
            int idx = tid + i * 256;
            uint32_t row = idx >> 2, q = idx & 3;
            cpasync16(stb + 8192 + swz(row, q), pBh + (size_t)row * E_DIM + k0 + q * 8);
            cpasync16(stb + 16384 + swz(row, q), pBl + (size_t)row * E_DIM + k0 + q * 8);
        }
    };

    float c[2][4][4];
    #pragma unroll
    for (int mi = 0; mi < 2; mi++)
        #pragma unroll
        for (int ni = 0; ni < 4; ni++)
            #pragma unroll
            for (int e = 0; e < 4; e++) c[mi][ni][e] = 0.f;

    const uint32_t aRow = wm * 32 + (lane & 15);
    const uint32_t aCh = lane >> 4;
    const uint32_t bGrp = lane >> 3, bRin = lane & 7;
    const uint32_t bRowBase = wn * 32 + ((bGrp >> 1) << 3) + bRin;
    const uint32_t bCh = bGrp & 1;

    issue(0, 0); CP_COMMIT();
    issue(1, 1); CP_COMMIT();

    for (int kc = 0; kc < 32; kc++) {
        const int buf = kc % 3;
        if (kc < 31) { CP_WAIT(1); } else { CP_WAIT(0); }
        __syncthreads();
        if (kc + 2 < 32) { issue((kc + 2) % 3, kc + 2); CP_COMMIT(); }

        const uint32_t saH = sb + buf * STG64_B;
        const uint32_t saL = saH + 4096;
        const uint32_t sbH = saH + 8192;
        const uint32_t sbL = saH + 16384;

        #pragma unroll
        for (int ks = 0; ks < 2; ks++) {
            uint32_t ah[2][4], al[2][4], bh[4][2], bl[4][2];
            #pragma unroll
            for (int mi = 0; mi < 2; mi++) {
                uint32_t off = swz(aRow + mi * 16, ks * 2 + aCh);
                ldsm4(ah[mi], saH + off);
                ldsm4(al[mi], saL + off);
            }
            #pragma unroll
            for (int half = 0; half < 2; half++) {
                uint32_t off = swz(bRowBase + half * 16, ks * 2 + bCh);
                ldsm4(&bh[half * 2][0], sbH + off);
                ldsm4(&bl[half * 2][0], sbL + off);
            }
            #pragma unroll
            for (int mi = 0; mi < 2; mi++)
                #pragma unroll
                for (int ni = 0; ni < 4; ni++) {
                    mma16816(c[mi][ni], ah[mi], bh[ni]);
                    mma16816(c[mi][ni], ah[mi], bl[ni]);
                    mma16816(c[mi][ni], al[mi], bh[ni]);
                }
        }
    }

    const int rBase = m0 + wm * 32 + (lane >> 2);
    const int nBase = n0 + wn * 32 + (lane & 3) * 2;
    #pragma unroll
    for (int mi = 0; mi < 2; mi++) {
        #pragma unroll
        for (int ni = 0; ni < 4; ni++) {
            int n = nBase + ni * 8;
            #pragma unroll
            for (int half = 0; half < 2; half++) {
                int row = rBase + mi * 16 + half * 8;
                float v0 = c[mi][ni][half * 2 + 0];
                float v1 = c[mi][ni][half * 2 + 1];
                if (mode == 0) {
                    const int z = n >> 10;
                    const float* bias = z == 0 ? bias0 : z == 1 ? bias1 : bias2;
                    __nv_bfloat16* dh = z == 0 ? g_qh : z == 1 ? g_kh : g_vh;
                    __nv_bfloat16* dl = z == 0 ? g_ql : z == 1 ? g_kl : g_vl;
                    const int h = (n >> 6) & 15, d = n & 63, bi = n & 1023;
                    const float scl = (z == 0) ? 0.125f : 1.0f;
                    float a = (v0 + __ldg(&bias[bi + 0])) * scl;
                    float b = (v1 + __ldg(&bias[bi + 1])) * scl;
                    size_t o = ((size_t)h * S_LEN + row) * DH + d;
                    splitstore2(a, b, dh + o, dl + o);
                } else {
                    float2 o;
                    o.x = v0 + __ldg(&bias0[n + 0]);
                    o.y = v1 + __ldg(&bias0[n + 1]);
                    *(float2*)&out[(size_t)row * E_DIM + n] = o;
                }
            }
        }
    }
}

// ---------------------------------------------------------------------------
// Split-KV tensor-core causal flash attention (unchanged from R13).
// ---------------------------------------------------------------------------
#define KV_TILE_B  8192
#define KV_STAGE_B 32768
#define ATN_SMEM_BYTES (2 * KV_STAGE_B)   // 65536

__global__ __launch_bounds__(128, 3) void attn_mma_kernel()
{
    extern __shared__ __nv_bfloat16 as2[];
    const uint32_t sbq = smem_to_u32(as2);
    const int tid = threadIdx.x, lane = tid & 31, w = tid >> 5;
    const int i0    = ((int)gridDim.x >> 1) - 1 - ((int)blockIdx.x >> 1);
    const int split = blockIdx.x & 1;
    const int h = blockIdx.y;

    const int total = i0 + 1;
    const int half  = (total + 1) >> 1;
    const int jb = split ? half : 0;
    const int je = split ? total : half;

    const int rowq = lane >> 2, colq = (lane & 3) * 2;
    const size_t pbase = ((size_t)(split * NH + h) * S_LEN) + i0 * 64;

    if (jb >= je) {
        const int r0 = w * 16 + rowq;
        #pragma unroll
        for (int ni = 0; ni < 8; ni++) {
            const int col = colq + ni * 8;
            float2 z2 = make_float2(0.f, 0.f);
            *(float2*)&g_opart[(pbase + r0) * DH + col] = z2;
            *(float2*)&g_opart[(pbase + r0 + 8) * DH + col] = z2;
        }
        if ((lane & 3) == 0) {
            g_mpart[pbase + r0] = -1e30f;
            g_mpart[pbase + r0 + 8] = -1e30f;
            g_lpart[pbase + r0] = 0.f;
            g_lpart[pbase + r0 + 8] = 0.f;
        }
        return;
    }

    auto load_kv = [&](int s, int jt) {
        const size_t gofs = ((size_t)h * S_LEN + jt * 64) * DH;
        const __nv_bfloat16* src[4] = { g_kh + gofs, g_kl + gofs,
                                        g_vh + gofs, g_vl + gofs };
        const uint32_t stb = sbq + s * KV_STAGE_B;
        #pragma unroll
        for (int t = 0; t < 4; t++) {
            const uint32_t db = stb + t * KV_TILE_B;
            #pragma unroll
            for (int i = 0; i < 4; i++) {
                int idx = tid + i * 128;
                uint32_t row = idx >> 3, q = idx & 7;
                cpasync16(db + swz8(row, q), src[t] + row * 64 + q * 8);
            }
        }
    };

    load_kv(0, jb);
    CP_COMMIT();

    const __nv_bfloat16* Qh = g_qh + ((size_t)h * S_LEN + i0 * 64) * DH;
    const __nv_bfloat16* Ql = g_ql + ((size_t)h * S_LEN + i0 * 64) * DH;
    uint32_t aQh[4][4], aQl[4][4];
    {
        const int qr = w * 16 + rowq;
        const int qc = colq;
        #pragma unroll
        for (int ks = 0; ks < 4; ks++) {
            const __nv_bfloat16* ph = Qh + (size_t)qr * DH + ks * 16 + qc;
            const __nv_bfloat16* pl = Ql + (size_t)qr * DH + ks * 16 + qc;
            aQh[ks][0] = *(const uint32_t*)(ph);
            aQh[ks][1] = *(const uint32_t*)(ph + 8 * DH);
            aQh[ks][2] = *(const uint32_t*)(ph + 8);
            aQh[ks][3] = *(const uint32_t*)(ph + 8 * DH + 8);
            aQl[ks][0] = *(const uint32_t*)(pl);
            aQl[ks][1] = *(const uint32_t*)(pl + 8 * DH);
            aQl[ks][2] = *(const uint32_t*)(pl + 8);
            aQl[ks][3] = *(const uint32_t*)(pl + 8 * DH + 8);
        }
    }

    float m0 = -1e30f, m1 = -1e30f, l0 = 0.f, l1 = 0.f;
    float oc[8][4];
    #pragma unroll
    for (int ni = 0; ni < 8; ni++)
        #pragma unroll
        for (int e = 0; e < 4; e++) oc[ni][e] = 0.f;

    const int grp = lane >> 3, rin = lane & 7;

    for (int jt = jb; jt < je; jt++) {
        const int buf = (jt - jb) & 1;
        CP_WAIT(0);
        __syncthreads();
        if (jt + 1 < je) { load_kv(buf ^ 1, jt + 1); CP_COMMIT(); }

        const uint32_t stb = sbq + buf * KV_STAGE_B;
        const uint32_t sKh = stb, sKl = stb + KV_TILE_B;
        const uint32_t sVh = stb + 2 * KV_TILE_B, sVl = stb + 3 * KV_TILE_B;

        float sc[8][4];
        #pragma unroll
        for (int ni = 0; ni < 8; ni++)
            #pragma unroll
            for (int e = 0; e < 4; e++) sc[ni][e] = 0.f;

        #pragma unroll
        for (int ks = 0; ks < 4; ks++) {
            #pragma unroll
            for (int g = 0; g < 4; g++) {
                uint32_t kh[4], kl[4];
                uint32_t off = swz8(g * 16 + ((grp >> 1) << 3) + rin,
                                    ks * 2 + (grp & 1));
                ldsm4(kh, sKh + off);
                ldsm4(kl, sKl + off);
                mma16816(sc[2 * g],     aQh[ks], kh);
                mma16816(sc[2 * g],     aQh[ks], kl);
                mma16816(sc[2 * g],     aQl[ks], kh);
                mma16816(sc[2 * g + 1], aQh[ks], kh + 2);
                mma16816(sc[2 * g + 1], aQh[ks], kl + 2);
                mma16816(sc[2 * g + 1], aQl[ks], kh + 2);
            }
        }

        if (jt == i0) {
            const int rowL0 = w * 16 + rowq, rowL1 = rowL0 + 8;
            #pragma unroll
            for (int ni = 0; ni < 8; ni++) {
                int colL = ni * 8 + colq;
                if (colL     > rowL0) sc[ni][0] = -1e30f;
                if (colL + 1 > rowL0) sc[ni][1] = -1e30f;
                if (colL     > rowL1) sc[ni][2] = -1e30f;
                if (colL + 1 > rowL1) sc[ni][3] = -1e30f;
            }
        }

        float t0 = -1e30f, t1 = -1e30f;
        #pragma unroll
        for (int ni = 0; ni < 8; ni++) {
            t0 = fmaxf(t0, fmaxf(sc[ni][0], sc[ni][1]));
            t1 = fmaxf(t1, fmaxf(sc[ni][2], sc[ni][3]));
        }
        t0 = fmaxf(t0, __shfl_xor_sync(0xffffffffu, t0, 1));
        t0 = fmaxf(t0, __shfl_xor_sync(0xffffffffu, t0, 2));
        t1 = fmaxf(t1, __shfl_xor_sync(0xffffffffu, t1, 1));
        t1 = fmaxf(t1, __shfl_xor_sync(0xffffffffu, t1, 2));
        const float m0n = fmaxf(m0, t0), m1n = fmaxf(m1, t1);
        const float f0 = __expf(m0 - m0n), f1 = __expf(m1 - m1n);

        float rs0 = 0.f, rs1 = 0.f;
        #pragma unroll
        for (int ni = 0; ni < 8; ni++) {
            sc[ni][0] = __expf(sc[ni][0] - m0n); rs0 += sc[ni][0];
            sc[ni][1] = __expf(sc[ni][1] - m0n); rs0 += sc[ni][1];
            sc[ni][2] = __expf(sc[ni][2] - m1n); rs1 += sc[ni][2];
            sc[ni][3] = __expf(sc[ni][3] - m1n); rs1 += sc[ni][3];
        }
        rs0 += __shfl_xor_sync(0xffffffffu, rs0, 1);
        rs0 += __shfl_xor_sync(0xffffffffu, rs0, 2);
        rs1 += __shfl_xor_sync(0xffffffffu, rs1, 1);
        rs1 += __shfl_xor_sync(0xffffffffu, rs1, 2);
        l0 = l0 * f0 + rs0; l1 = l1 * f1 + rs1;
        m0 = m0n; m1 = m1n;
        #pragma unroll
        for (int ni = 0; ni < 8; ni++) {
            oc[ni][0] *= f0; oc[ni][1] *= f0;
            oc[ni][2] *= f1; oc[ni][3] *= f1;
        }

        uint32_t aPh[4][4], aPl[4][4];
        #pragma unroll
        for (int ks = 0; ks < 4; ks++) {
            const int ta = 2 * ks, tb = 2 * ks + 1;
            packsplit2(sc[ta][0], sc[ta][1], aPh[ks][0], aPl[ks][0]);
            packsplit2(sc[ta][2], sc[ta][3], aPh[ks][1], aPl[ks][1]);
            packsplit2(sc[tb][0], sc[tb][1], aPh[ks][2], aPl[ks][2]);
            packsplit2(sc[tb][2], sc[tb][3], aPh[ks][3], aPl[ks][3]);
        }

        #pragma unroll
        for (int ks = 0; ks < 4; ks++) {
            #pragma unroll
            for (int g = 0; g < 4; g++) {
                uint32_t vh[4], vl[4];
                uint32_t off = swz8(ks * 16 + ((grp & 1) << 3) + rin,
                                    g * 2 + (grp >> 1));
                ldsm4t(vh, sVh + off);
                ldsm4t(vl, sVl + off);
                mma16816(oc[2 * g],     aPh[ks], vh);
                mma16816(oc[2 * g],     aPh[ks], vl);
                mma16816(oc[2 * g],     aPl[ks], vh);
                mma16816(oc[2 * g + 1], aPh[ks], vh + 2);
                mma16816(oc[2 * g + 1], aPh[ks], vl + 2);
                mma16816(oc[2 * g + 1], aPl[ks], vh + 2);
            }
        }
    }

    const int r0 = w * 16 + rowq;
    #pragma unroll
    for (int ni = 0; ni < 8; ni++) {
        const int col = colq + ni * 8;
        *(float2*)&g_opart[(pbase + r0) * DH + col] =
            make_float2(oc[ni][0], oc[ni][1]);
        *(float2*)&g_opart[(pbase + r0 + 8) * DH + col] =
            make_float2(oc[ni][2], oc[ni][3]);
    }
    if ((lane & 3) == 0) {
        g_mpart[pbase + r0] = m0;     g_lpart[pbase + r0] = l0;
        g_mpart[pbase + r0 + 8] = m1; g_lpart[pbase + r0 + 8] = l1;
    }
}

// ---------------------------------------------------------------------------
// Combine partials -> g_aoh/g_aol. grid = 4096 x 256.
// ---------------------------------------------------------------------------
__global__ __launch_bounds__(256) void attn_combine_kernel()
{
    const int idx = blockIdx.x * 256 + threadIdx.x;
    const int hrow = idx >> 5;
    const int d2 = (idx & 31) * 2;
    const int row = hrow & (S_LEN - 1);
    const int h = hrow >> 11;

    const float m0 = __ldg(&g_mpart[hrow]);
    const float m1 = __ldg(&g_mpart[NH * S_LEN + hrow]);
    const float l0 = __ldg(&g_lpart[hrow]);
    const float l1 = __ldg(&g_lpart[NH * S_LEN + hrow]);
    const float M = fmaxf(m0, m1);
    const float e0 = __expf(m0 - M), e1 = __expf(m1 - M);
    const float inv = 1.f / (l0 * e0 + l1 * e1);

    float2 O0 = *(const float2*)&g_opart[(size_t)hrow * DH + d2];
    float2 O1 = *(const float2*)&g_opart[(size_t)(NH * S_LEN + hrow) * DH + d2];
    float a = (O0.x * e0 + O1.x * e1) * inv;
    float b = (O0.y * e0 + O1.y * e1) * inv;

    size_t o = (size_t)row * E_DIM + h * DH + d2;
    splitstore2(a, b, g_aoh + o, g_aol + o);
}

// ---------------------------------------------------------------------------
extern "C" void kernel_launch(void* const* d_in, const int* in_sizes, int n_in,
                              void* d_out, int out_size)
{
    const float* x  = (const float*)d_in[0];
    const float* Wq = (const float*)d_in[1];
    const float* bq = (const float*)d_in[2];
    const float* Wk = (const float*)d_in[3];
    const float* bk = (const float*)d_in[4];
    const float* Wv = (const float*)d_in[5];
    const float* bv = (const float*)d_in[6];
    const float* Wo = (const float*)d_in[7];
    const float* bo = (const float*)d_in[8];
    float* out = (float*)d_out;

    (void)in_sizes; (void)n_in; (void)out_size;

    cudaFuncSetAttribute(gemm64_mma_kernel,
                         cudaFuncAttributeMaxDynamicSharedMemorySize, GEMM64_SMEM_BYTES);
    cudaFuncSetAttribute(attn_mma_kernel,
                         cudaFuncAttributeMaxDynamicSharedMemorySize, ATN_SMEM_BYTES);

    prep_kernel<<<dim3(16, 16, 12), 256>>>(x, Wq, Wk, Wv, Wo);
    gemm64_mma_kernel<<<dim3(32, 24), 256, GEMM64_SMEM_BYTES>>>(0, bq, bk, bv, nullptr);
    attn_mma_kernel<<<dim3(64, NH), 128, ATN_SMEM_BYTES>>>();
    attn_combine_kernel<<<4096, 256>>>();
    gemm64_mma_kernel<<<dim3(32, 8), 256, GEMM64_SMEM_BYTES>>>(1, bo, nullptr, nullptr, out);
}

// round 15
// speedup vs baseline: 1.0677x; 1.0677x over previous
#include <cuda_runtime.h>
#include <cuda_bf16.h>
#include <cstdint>
#include <math.h>

#define S_LEN 2048
#define E_DIM 1024
#define NH    16
#define DH    64

// ---------------------------------------------------------------------------
// Scratch (__device__ globals; allocation-free rule)
// ---------------------------------------------------------------------------
__device__ __align__(16) __nv_bfloat16 g_qh[NH * S_LEN * DH];
__device__ __align__(16) __nv_bfloat16 g_ql[NH * S_LEN * DH];
__device__ __align__(16) __nv_bfloat16 g_kh[NH * S_LEN * DH];
__device__ __align__(16) __nv_bfloat16 g_kl[NH * S_LEN * DH];
__device__ __align__(16) __nv_bfloat16 g_vh[NH * S_LEN * DH];
__device__ __align__(16) __nv_bfloat16 g_vl[NH * S_LEN * DH];

__device__ __align__(16) __nv_bfloat16 g_xh[S_LEN * E_DIM];
__device__ __align__(16) __nv_bfloat16 g_xl[S_LEN * E_DIM];
__device__ __align__(16) __nv_bfloat16 g_wth[3 * E_DIM * E_DIM];
__device__ __align__(16) __nv_bfloat16 g_wtl[3 * E_DIM * E_DIM];
__device__ __align__(16) __nv_bfloat16 g_woth[E_DIM * E_DIM];
__device__ __align__(16) __nv_bfloat16 g_wotl[E_DIM * E_DIM];
__device__ __align__(16) __nv_bfloat16 g_aoh[S_LEN * E_DIM];
__device__ __align__(16) __nv_bfloat16 g_aol[S_LEN * E_DIM];

// split-KV partials
__device__ __align__(16) float g_opart[2 * NH * S_LEN * DH];
__device__ __align__(16) float g_mpart[2 * NH * S_LEN];
__device__ __align__(16) float g_lpart[2 * NH * S_LEN];

// ---------------------------------------------------------------------------
// Baseline-PTX helpers
// ---------------------------------------------------------------------------
__device__ __forceinline__ uint32_t smem_to_u32(const void* p) {
    uint32_t a;
    asm("{ .reg .u64 t; cvta.to.shared.u64 t, %1; cvt.u32.u64 %0, t; }"
        : "=r"(a) : "l"(p));
    return a;
}

__device__ __forceinline__ void ldsm4(uint32_t* r, uint32_t addr) {
    asm volatile("ldmatrix.sync.aligned.m8n8.x4.shared.b16 {%0,%1,%2,%3}, [%4];"
        : "=r"(r[0]), "=r"(r[1]), "=r"(r[2]), "=r"(r[3]) : "r"(addr));
}
__device__ __forceinline__ void ldsm4t(uint32_t* r, uint32_t addr) {
    asm volatile("ldmatrix.sync.aligned.m8n8.x4.trans.shared.b16 {%0,%1,%2,%3}, [%4];"
        : "=r"(r[0]), "=r"(r[1]), "=r"(r[2]), "=r"(r[3]) : "r"(addr));
}

__device__ __forceinline__ void mma16816(float* c, const uint32_t* a, const uint32_t* b) {
    asm volatile(
        "mma.sync.aligned.m16n8k16.row.col.f32.bf16.bf16.f32 "
        "{%0,%1,%2,%3}, {%4,%5,%6,%7}, {%8,%9}, {%0,%1,%2,%3};"
        : "+f"(c[0]), "+f"(c[1]), "+f"(c[2]), "+f"(c[3])
        : "r"(a[0]), "r"(a[1]), "r"(a[2]), "r"(a[3]), "r"(b[0]), "r"(b[1]));
}

__device__ __forceinline__ void cpasync16(uint32_t saddr, const void* gaddr) {
    asm volatile("cp.async.cg.shared.global [%0], [%1], 16;"
        :: "r"(saddr), "l"(gaddr) : "memory");
}
#define CP_COMMIT() asm volatile("cp.async.commit_group;" ::: "memory")
#define CP_WAIT(n)  asm volatile("cp.async.wait_group %0;" :: "n"(n) : "memory")

__device__ __forceinline__ void split1(float v, __nv_bfloat16& h, __nv_bfloat16& l) {
    h = __float2bfloat16(v);
    l = __float2bfloat16(v - __bfloat162float(h));
}
__device__ __forceinline__ void packsplit2(float a, float b, uint32_t& hi, uint32_t& lo) {
    __nv_bfloat162 h, l;
    h.x = __float2bfloat16(a); h.y = __float2bfloat16(b);
    l.x = __float2bfloat16(a - __bfloat162float(h.x));
    l.y = __float2bfloat16(b - __bfloat162float(h.y));
    hi = *(uint32_t*)&h; lo = *(uint32_t*)&l;
}
__device__ __forceinline__ void splitstore2(float a, float b,
                                            __nv_bfloat16* ph, __nv_bfloat16* pl) {
    __nv_bfloat162 h, l;
    h.x = __float2bfloat16(a); h.y = __float2bfloat16(b);
    l.x = __float2bfloat16(a - __bfloat162float(h.x));
    l.y = __float2bfloat16(b - __bfloat162float(h.y));
    *(__nv_bfloat162*)ph = h; *(__nv_bfloat162*)pl = l;
}

// swizzled byte offset, 64B rows (4x16B chunks)
__device__ __forceinline__ uint32_t swz(uint32_t row, uint32_t chunk) {
    return row * 64 + ((chunk ^ ((row >> 1) & 3)) << 4);
}
// swizzled byte offset, 128B rows (8x16B chunks)
__device__ __forceinline__ uint32_t swz8(uint32_t row, uint32_t chunk) {
    return row * 128 + ((chunk ^ (row & 7)) << 4);
}

// ---------------------------------------------------------------------------
// Merged prologue: z<3 Wqkv, z==3 Wo, z>=4 x split. grid(16,16,12)
// ---------------------------------------------------------------------------
__global__ __launch_bounds__(256) void prep_kernel(
    const float* __restrict__ x,
    const float* __restrict__ Wq, const float* __restrict__ Wk,
    const float* __restrict__ Wv, const float* __restrict__ Wo)
{
    const int z = blockIdx.z;
    const int tid = threadIdx.x;

    if (z < 3) {
        __shared__ float s[64][65];
        const int h = blockIdx.y, e0 = blockIdx.x * 64;
        const float* W = (z == 0 ? Wq : z == 1 ? Wk : Wv) + (size_t)h * E_DIM * DH;
        #pragma unroll
        for (int i = 0; i < 16; i++) {
            int idx = tid + i * 256;
            int e = idx >> 6, d = idx & 63;
            s[d][e] = W[(size_t)(e0 + e) * DH + d];
        }
        __syncthreads();
        const int nb = z * 1024 + h * 64;
        #pragma unroll
        for (int i = 0; i < 16; i++) {
            int idx = tid + i * 256;
            int d = idx >> 6, e = idx & 63;
            __nv_bfloat16 hh, ll;
            split1(s[d][e], hh, ll);
            g_wth[(size_t)(nb + d) * E_DIM + e0 + e] = hh;
            g_wtl[(size_t)(nb + d) * E_DIM + e0 + e] = ll;
        }
    } else if (z == 3) {
        __shared__ float s[64][65];
        const int f0 = blockIdx.x * 64, e0 = blockIdx.y * 64;
        #pragma unroll
        for (int i = 0; i < 16; i++) {
            int idx = tid + i * 256;
            int fl = idx >> 6, el = idx & 63;
            s[el][fl] = Wo[(size_t)(f0 + fl) * E_DIM + e0 + el];
        }
        __syncthreads();
        #pragma unroll
        for (int i = 0; i < 16; i++) {
            int idx = tid + i * 256;
            int el = idx >> 6, fl = idx & 63;
            __nv_bfloat16 hh, ll;
            split1(s[el][fl], hh, ll);
            g_woth[(size_t)(e0 + el) * E_DIM + f0 + fl] = hh;
            g_wotl[(size_t)(e0 + el) * E_DIM + f0 + fl] = ll;
        }
    } else {
        const int lb = (z - 4) * 256 + blockIdx.y * 16 + blockIdx.x;
        int i = (lb * 256 + tid) * 4;
        float4 v = *(const float4*)(x + i);
        splitstore2(v.x, v.y, g_xh + i, g_xl + i);
        splitstore2(v.z, v.w, g_xh + i + 2, g_xl + i + 2);
    }
}

// ---------------------------------------------------------------------------
// QKV GEMM: BM=64 / BN=128, 128 threads (4 warps, 1x4), 3 CTAs/SM.
// grid (32, 24) = 768 tiles over 444 slots = 1.73 waves.
// stage = Ah(4K)+Al(4K)+Bh(8K)+Bl(8K) = 24KB; 3 stages = 72KB.
// ---------------------------------------------------------------------------
#define STGQ_B 24576
#define GEMMQ_SMEM_BYTES (3 * STGQ_B)

__global__ __launch_bounds__(128, 3) void gemm_qkv_kernel(
    const float* __restrict__ bias0, const float* __restrict__ bias1,
    const float* __restrict__ bias2)
{
    extern __shared__ __nv_bfloat16 gsq[];
    const uint32_t sb = smem_to_u32(gsq);
    const int tid = threadIdx.x;
    const int wid = tid >> 5, lane = tid & 31;
    const int wn = wid;                       // 1 x 4 warp grid
    const int m0 = blockIdx.x * 64, n0 = blockIdx.y * 128;

    const __nv_bfloat16* pAh = g_xh + (size_t)m0 * E_DIM;
    const __nv_bfloat16* pAl = g_xl + (size_t)m0 * E_DIM;
    const __nv_bfloat16* pBh = g_wth + (size_t)n0 * E_DIM;
    const __nv_bfloat16* pBl = g_wtl + (size_t)n0 * E_DIM;

    auto issue = [&](int s, int kc) {
        const int k0 = kc * 32;
        const uint32_t stb = sb + s * STGQ_B;
        #pragma unroll
        for (int i = 0; i < 2; i++) {     // A: 64 rows x 4 chunks = 256 items
            int idx = tid + i * 128;
            uint32_t row = idx >> 2, q = idx & 3;
            cpasync16(stb + swz(row, q), pAh + (size_t)row * E_DIM + k0 + q * 8);
            cpasync16(stb + 4096 + swz(row, q), pAl + (size_t)row * E_DIM + k0 + q * 8);
        }
        #pragma unroll
        for (int i = 0; i < 4; i++) {     // B: 128 rows x 4 chunks = 512 items
            int idx = tid + i * 128;
            uint32_t row = idx >> 2, q = idx & 3;
            cpasync16(stb + 8192 + swz(row, q), pBh + (size_t)row * E_DIM + k0 + q * 8);
            cpasync16(stb + 16384 + swz(row, q), pBl + (size_t)row * E_DIM + k0 + q * 8);
        }
    };

    float c[4][4][4];
    #pragma unroll
    for (int mi = 0; mi < 4; mi++)
        #pragma unroll
        for (int ni = 0; ni < 4; ni++)
            #pragma unroll
            for (int e = 0; e < 4; e++) c[mi][ni][e] = 0.f;

    const uint32_t aRow = lane & 15;
    const uint32_t aCh = lane >> 4;
    const uint32_t bGrp = lane >> 3, bRin = lane & 7;
    const uint32_t bRowBase = wn * 32 + ((bGrp >> 1) << 3) + bRin;
    const uint32_t bCh = bGrp & 1;

    issue(0, 0); CP_COMMIT();
    issue(1, 1); CP_COMMIT();

    for (int kc = 0; kc < 32; kc++) {
        const int buf = kc % 3;
        if (kc < 31) { CP_WAIT(1); } else { CP_WAIT(0); }
        __syncthreads();
        if (kc + 2 < 32) { issue((kc + 2) % 3, kc + 2); CP_COMMIT(); }

        const uint32_t saH = sb + buf * STGQ_B;
        const uint32_t saL = saH + 4096;
        const uint32_t sbH = saH + 8192;
        const uint32_t sbL = saH + 16384;

        #pragma unroll
        for (int ks = 0; ks < 2; ks++) {
            uint32_t ah[4][4], al[4][4], bh[4][2], bl[4][2];
            #pragma unroll
            for (int mi = 0; mi < 4; mi++) {
                uint32_t off = swz(aRow + mi * 16, ks * 2 + aCh);
                ldsm4(ah[mi], saH + off);
                ldsm4(al[mi], saL + off);
            }
            #pragma unroll
            for (int half = 0; half < 2; half++) {
                uint32_t off = swz(bRowBase + half * 16, ks * 2 + bCh);
                ldsm4(&bh[half * 2][0], sbH + off);
                ldsm4(&bl[half * 2][0], sbL + off);
            }
            #pragma unroll
            for (int mi = 0; mi < 4; mi++)
                #pragma unroll
                for (int ni = 0; ni < 4; ni++) {
                    mma16816(c[mi][ni], ah[mi], bh[ni]);
                    mma16816(c[mi][ni], ah[mi], bl[ni]);
                    mma16816(c[mi][ni], al[mi], bh[ni]);
                }
        }
    }

    const int rBase = m0 + (lane >> 2);
    const int nBase = n0 + wn * 32 + (lane & 3) * 2;
    #pragma unroll
    for (int mi = 0; mi < 4; mi++) {
        #pragma unroll
        for (int ni = 0; ni < 4; ni++) {
            int n = nBase + ni * 8;
            #pragma unroll
            for (int half = 0; half < 2; half++) {
                int row = rBase + mi * 16 + half * 8;
                float v0 = c[mi][ni][half * 2 + 0];
                float v1 = c[mi][ni][half * 2 + 1];
                const int z = n >> 10;
                const float* bias = z == 0 ? bias0 : z == 1 ? bias1 : bias2;
                __nv_bfloat16* dh = z == 0 ? g_qh : z == 1 ? g_kh : g_vh;
                __nv_bfloat16* dl = z == 0 ? g_ql : z == 1 ? g_kl : g_vl;
                const int h = (n >> 6) & 15, d = n & 63, bi = n & 1023;
                const float scl = (z == 0) ? 0.125f : 1.0f;
                float a = (v0 + __ldg(&bias[bi + 0])) * scl;
                float b = (v1 + __ldg(&bias[bi + 1])) * scl;
                size_t o = ((size_t)h * S_LEN + row) * DH + d;
                splitstore2(a, b, dh + o, dl + o);
            }
        }
    }
}

// ---------------------------------------------------------------------------
// Proj GEMM: BM=64, BN=128, 256 threads, 3-stage; grid (32, 8) = single wave.
// (R13-measured-good)
// ---------------------------------------------------------------------------
#define STG64_B 24576
#define GEMM64_SMEM_BYTES (3 * STG64_B)

__global__ __launch_bounds__(256, 2) void gemm_proj_kernel(
    const float* __restrict__ bo, float* __restrict__ out)
{
    extern __shared__ __nv_bfloat16 gs2[];
    const uint32_t sb = smem_to_u32(gs2);
    const int tid = threadIdx.x;
    const int wid = tid >> 5, lane = tid & 31;
    const int wm = wid >> 2, wn = wid & 3;
    const int m0 = blockIdx.x * 64, n0 = blockIdx.y * 128;

    const __nv_bfloat16* pAh = g_aoh + (size_t)m0 * E_DIM;
    const __nv_bfloat16* pAl = g_aol + (size_t)m0 * E_DIM;
    const __nv_bfloat16* pBh = g_woth + (size_t)n0 * E_DIM;
    const __nv_bfloat16* pBl = g_wotl + (size_t)n0 * E_DIM;

    auto issue = [&](int s, int kc) {
        const int k0 = kc * 32;
        const uint32_t stb = sb + s * STG64_B;
        {
            uint32_t row = tid >> 2, q = tid & 3;
            cpasync16(stb + swz(row, q), pAh + (size_t)row * E_DIM + k0 + q * 8);
            cpasync16(stb + 4096 + swz(row, q), pAl + (size_t)row * E_DIM + k0 + q * 8);
        }
        #pragma unroll
        for (int i = 0; i < 2; i++) {
            int idx = tid + i * 256;
            uint32_t row = idx >> 2, q = idx & 3;
            cpasync16(stb + 8192 + swz(row, q), pBh + (size_t)row * E_DIM + k0 + q * 8);
            cpasync16(stb + 16384 + swz(row, q), pBl + (size_t)row * E_DIM + k0 + q * 8);
        }
    };

    float c[2][4][4];
    #pragma unroll
    for (int mi = 0; mi < 2; mi++)
        #pragma unroll
        for (int ni = 0; ni < 4; ni++)
            #pragma unroll
            for (int e = 0; e < 4; e++) c[mi][ni][e] = 0.f;

    const uint32_t aRow = wm * 32 + (lane & 15);
    const uint32_t aCh = lane >> 4;
    const uint32_t bGrp = lane >> 3, bRin = lane & 7;
    const uint32_t bRowBase = wn * 32 + ((bGrp >> 1) << 3) + bRin;
    const uint32_t bCh = bGrp & 1;

    issue(0, 0); CP_COMMIT();
    issue(1, 1); CP_COMMIT();

    for (int kc = 0; kc < 32; kc++) {
        const int buf = kc % 3;
        if (kc < 31) { CP_WAIT(1); } else { CP_WAIT(0); }
        __syncthreads();
        if (kc + 2 < 32) { issue((kc + 2) % 3, kc + 2); CP_COMMIT(); }

        const uint32_t saH = sb + buf * STG64_B;
        const uint32_t saL = saH + 4096;
        const uint32_t sbH = saH + 8192;
        const uint32_t sbL = saH + 16384;

        #pragma unroll
        for (int ks = 0; ks < 2; ks++) {
            uint32_t ah[2][4], al[2][4], bh[4][2], bl[4][2];
            #pragma unroll
            for (int mi = 0; mi < 2; mi++) {
                uint32_t off = swz(aRow + mi * 16, ks * 2 + aCh);
                ldsm4(ah[mi], saH + off);
                ldsm4(al[mi], saL + off);
            }
            #pragma unroll
            for (int half = 0; half < 2; half++) {
                uint32_t off = swz(bRowBase + half * 16, ks * 2 + bCh);
                ldsm4(&bh[half * 2][0], sbH + off);
                ldsm4(&bl[half * 2][0], sbL + off);
            }
            #pragma unroll
            for (int mi = 0; mi < 2; mi++)
                #pragma unroll
                for (int ni = 0; ni < 4; ni++) {
                    mma16816(c[mi][ni], ah[mi], bh[ni]);
                    mma16816(c[mi][ni], ah[mi], bl[ni]);
                    mma16816(c[mi][ni], al[mi], bh[ni]);
                }
        }
    }

    const int rBase = m0 + wm * 32 + (lane >> 2);
    const int nBase = n0 + wn * 32 + (lane & 3) * 2;
    #pragma unroll
    for (int mi = 0; mi < 2; mi++) {
        #pragma unroll
        for (int ni = 0; ni < 4; ni++) {
            int n = nBase + ni * 8;
            #pragma unroll
            for (int half = 0; half < 2; half++) {
                int row = rBase + mi * 16 + half * 8;
                float2 o;
                o.x = c[mi][ni][half * 2 + 0] + __ldg(&bo[n + 0]);
                o.y = c[mi][ni][half * 2 + 1] + __ldg(&bo[n + 1]);
                *(float2*)&out[(size_t)row * E_DIM + n] = o;
            }
        }
    }
}

// ---------------------------------------------------------------------------
// Split-KV tensor-core causal flash attention (unchanged from R13).
// ---------------------------------------------------------------------------
#define KV_TILE_B  8192
#define KV_STAGE_B 32768
#define ATN_SMEM_BYTES (2 * KV_STAGE_B)   // 65536

__global__ __launch_bounds__(128, 3) void attn_mma_kernel()
{
    extern __shared__ __nv_bfloat16 as2[];
    const uint32_t sbq = smem_to_u32(as2);
    const int tid = threadIdx.x, lane = tid & 31, w = tid >> 5;
    const int i0    = ((int)gridDim.x >> 1) - 1 - ((int)blockIdx.x >> 1);
    const int split = blockIdx.x & 1;
    const int h = blockIdx.y;

    const int total = i0 + 1;
    const int half  = (total + 1) >> 1;
    const int jb = split ? half : 0;
    const int je = split ? total : half;

    const int rowq = lane >> 2, colq = (lane & 3) * 2;
    const size_t pbase = ((size_t)(split * NH + h) * S_LEN) + i0 * 64;

    if (jb >= je) {
        const int r0 = w * 16 + rowq;
        #pragma unroll
        for (int ni = 0; ni < 8; ni++) {
            const int col = colq + ni * 8;
            float2 z2 = make_float2(0.f, 0.f);
            *(float2*)&g_opart[(pbase + r0) * DH + col] = z2;
            *(float2*)&g_opart[(pbase + r0 + 8) * DH + col] = z2;
        }
        if ((lane & 3) == 0) {
            g_mpart[pbase + r0] = -1e30f;
            g_mpart[pbase + r0 + 8] = -1e30f;
            g_lpart[pbase + r0] = 0.f;
            g_lpart[pbase + r0 + 8] = 0.f;
        }
        return;
    }

    auto load_kv = [&](int s, int jt) {
        const size_t gofs = ((size_t)h * S_LEN + jt * 64) * DH;
        const __nv_bfloat16* src[4] = { g_kh + gofs, g_kl + gofs,
                                        g_vh + gofs, g_vl + gofs };
        const uint32_t stb = sbq + s * KV_STAGE_B;
        #pragma unroll
        for (int t = 0; t < 4; t++) {
            const uint32_t db = stb + t * KV_TILE_B;
            #pragma unroll
            for (int i = 0; i < 4; i++) {
                int idx = tid + i * 128;
                uint32_t row = idx >> 3, q = idx & 7;
                cpasync16(db + swz8(row, q), src[t] + row * 64 + q * 8);
            }
        }
    };

    load_kv(0, jb);
    CP_COMMIT();

    const __nv_bfloat16* Qh = g_qh + ((size_t)h * S_LEN + i0 * 64) * DH;
    const __nv_bfloat16* Ql = g_ql + ((size_t)h * S_LEN + i0 * 64) * DH;
    uint32_t aQh[4][4], aQl[4][4];
    {
        const int qr = w * 16 + rowq;
        const int qc = colq;
        #pragma unroll
        for (int ks = 0; ks < 4; ks++) {
            const __nv_bfloat16* ph = Qh + (size_t)qr * DH + ks * 16 + qc;
            const __nv_bfloat16* pl = Ql + (size_t)qr * DH + ks * 16 + qc;
            aQh[ks][0] = *(const uint32_t*)(ph);
            aQh[ks][1] = *(const uint32_t*)(ph + 8 * DH);
            aQh[ks][2] = *(const uint32_t*)(ph + 8);
            aQh[ks][3] = *(const uint32_t*)(ph + 8 * DH + 8);
            aQl[ks][0] = *(const uint32_t*)(pl);
            aQl[ks][1] = *(const uint32_t*)(pl + 8 * DH);
            aQl[ks][2] = *(const uint32_t*)(pl + 8);
            aQl[ks][3] = *(const uint32_t*)(pl + 8 * DH + 8);
        }
    }

    float m0 = -1e30f, m1 = -1e30f, l0 = 0.f, l1 = 0.f;
    float oc[8][4];
    #pragma unroll
    for (int ni = 0; ni < 8; ni++)
        #pragma unroll
        for (int e = 0; e < 4; e++) oc[ni][e] = 0.f;

    const int grp = lane >> 3, rin = lane & 7;

    for (int jt = jb; jt < je; jt++) {
        const int buf = (jt - jb) & 1;
        CP_WAIT(0);
        __syncthreads();
        if (jt + 1 < je) { load_kv(buf ^ 1, jt + 1); CP_COMMIT(); }

        const uint32_t stb = sbq + buf * KV_STAGE_B;
        const uint32_t sKh = stb, sKl = stb + KV_TILE_B;
        const uint32_t sVh = stb + 2 * KV_TILE_B, sVl = stb + 3 * KV_TILE_B;

        float sc[8][4];
        #pragma unroll
        for (int ni = 0; ni < 8; ni++)
            #pragma unroll
            for (int e = 0; e < 4; e++) sc[ni][e] = 0.f;

        #pragma unroll
        for (int ks = 0; ks < 4; ks++) {
            #pragma unroll
            for (int g = 0; g < 4; g++) {
                uint32_t kh[4], kl[4];
                uint32_t off = swz8(g * 16 + ((grp >> 1) << 3) + rin,
                                    ks * 2 + (grp & 1));
                ldsm4(kh, sKh + off);
                ldsm4(kl, sKl + off);
                mma16816(sc[2 * g],     aQh[ks], kh);
                mma16816(sc[2 * g],     aQh[ks], kl);
                mma16816(sc[2 * g],     aQl[ks], kh);
                mma16816(sc[2 * g + 1], aQh[ks], kh + 2);
                mma16816(sc[2 * g + 1], aQh[ks], kl + 2);
                mma16816(sc[2 * g + 1], aQl[ks], kh + 2);
            }
        }

        if (jt == i0) {
            const int rowL0 = w * 16 + rowq, rowL1 = rowL0 + 8;
            #pragma unroll
            for (int ni = 0; ni < 8; ni++) {
                int colL = ni * 8 + colq;
                if (colL     > rowL0) sc[ni][0] = -1e30f;
                if (colL + 1 > rowL0) sc[ni][1] = -1e30f;
                if (colL     > rowL1) sc[ni][2] = -1e30f;
                if (colL + 1 > rowL1) sc[ni][3] = -1e30f;
            }
        }

        float t0 = -1e30f, t1 = -1e30f;
        #pragma unroll
        for (int ni = 0; ni < 8; ni++) {
            t0 = fmaxf(t0, fmaxf(sc[ni][0], sc[ni][1]));
            t1 = fmaxf(t1, fmaxf(sc[ni][2], sc[ni][3]));
        }
        t0 = fmaxf(t0, __shfl_xor_sync(0xffffffffu, t0, 1));
        t0 = fmaxf(t0, __shfl_xor_sync(0xffffffffu, t0, 2));
        t1 = fmaxf(t1, __shfl_xor_sync(0xffffffffu, t1, 1));
        t1 = fmaxf(t1, __shfl_xor_sync(0xffffffffu, t1, 2));
        const float m0n = fmaxf(m0, t0), m1n = fmaxf(m1, t1);
        const float f0 = __expf(m0 - m0n), f1 = __expf(m1 - m1n);

        float rs0 = 0.f, rs1 = 0.f;
        #pragma unroll
        for (int ni = 0; ni < 8; ni++) {
            sc[ni][0] = __expf(sc[ni][0] - m0n); rs0 += sc[ni][0];
            sc[ni][1] = __expf(sc[ni][1] - m0n); rs0 += sc[ni][1];
            sc[ni][2] = __expf(sc[ni][2] - m1n); rs1 += sc[ni][2];
            sc[ni][3] = __expf(sc[ni][3] - m1n); rs1 += sc[ni][3];
        }
        rs0 += __shfl_xor_sync(0xffffffffu, rs0, 1);
        rs0 += __shfl_xor_sync(0xffffffffu, rs0, 2);
        rs1 += __shfl_xor_sync(0xffffffffu, rs1, 1);
        rs1 += __shfl_xor_sync(0xffffffffu, rs1, 2);
        l0 = l0 * f0 + rs0; l1 = l1 * f1 + rs1;
        m0 = m0n; m1 = m1n;
        #pragma unroll
        for (int ni = 0; ni < 8; ni++) {
            oc[ni][0] *= f0; oc[ni][1] *= f0;
            oc[ni][2] *= f1; oc[ni][3] *= f1;
        }

        uint32_t aPh[4][4], aPl[4][4];
        #pragma unroll
        for (int ks = 0; ks < 4; ks++) {
            const int ta = 2 * ks, tb = 2 * ks + 1;
            packsplit2(sc[ta][0], sc[ta][1], aPh[ks][0], aPl[ks][0]);
            packsplit2(sc[ta][2], sc[ta][3], aPh[ks][1], aPl[ks][1]);
            packsplit2(sc[tb][0], sc[tb][1], aPh[ks][2], aPl[ks][2]);
            packsplit2(sc[tb][2], sc[tb][3], aPh[ks][3], aPl[ks][3]);
        }

        #pragma unroll
        for (int ks = 0; ks < 4; ks++) {
            #pragma unroll
            for (int g = 0; g < 4; g++) {
                uint32_t vh[4], vl[4];
                uint32_t off = swz8(ks * 16 + ((grp & 1) << 3) + rin,
                                    g * 2 + (grp >> 1));
                ldsm4t(vh, sVh + off);
                ldsm4t(vl, sVl + off);
                mma16816(oc[2 * g],     aPh[ks], vh);
                mma16816(oc[2 * g],     aPh[ks], vl);
                mma16816(oc[2 * g],     aPl[ks], vh);
                mma16816(oc[2 * g + 1], aPh[ks], vh + 2);
                mma16816(oc[2 * g + 1], aPh[ks], vl + 2);
                mma16816(oc[2 * g + 1], aPl[ks], vh + 2);
            }
        }
    }

    const int r0 = w * 16 + rowq;
    #pragma unroll
    for (int ni = 0; ni < 8; ni++) {
        const int col = colq + ni * 8;
        *(float2*)&g_opart[(pbase + r0) * DH + col] =
            make_float2(oc[ni][0], oc[ni][1]);
        *(float2*)&g_opart[(pbase + r0 + 8) * DH + col] =
            make_float2(oc[ni][2], oc[ni][3]);
    }
    if ((lane & 3) == 0) {
        g_mpart[pbase + r0] = m0;     g_lpart[pbase + r0] = l0;
        g_mpart[pbase + r0 + 8] = m1; g_lpart[pbase + r0 + 8] = l1;
    }
}

// ---------------------------------------------------------------------------
// Combine partials -> g_aoh/g_aol. grid = 4096 x 256.
// ---------------------------------------------------------------------------
__global__ __launch_bounds__(256) void attn_combine_kernel()
{
    const int idx = blockIdx.x * 256 + threadIdx.x;
    const int hrow = idx >> 5;
    const int d2 = (idx & 31) * 2;
    const int row = hrow & (S_LEN - 1);
    const int h = hrow >> 11;

    const float m0 = __ldg(&g_mpart[hrow]);
    const float m1 = __ldg(&g_mpart[NH * S_LEN + hrow]);
    const float l0 = __ldg(&g_lpart[hrow]);
    const float l1 = __ldg(&g_lpart[NH * S_LEN + hrow]);
    const float M = fmaxf(m0, m1);
    const float e0 = __expf(m0 - M), e1 = __expf(m1 - M);
    const float inv = 1.f / (l0 * e0 + l1 * e1);

    float2 O0 = *(const float2*)&g_opart[(size_t)hrow * DH + d2];
    float2 O1 = *(const float2*)&g_opart[(size_t)(NH * S_LEN + hrow) * DH + d2];
    float a = (O0.x * e0 + O1.x * e1) * inv;
    float b = (O0.y * e0 + O1.y * e1) * inv;

    size_t o = (size_t)row * E_DIM + h * DH + d2;
    splitstore2(a, b, g_aoh + o, g_aol + o);
}

// ---------------------------------------------------------------------------
extern "C" void kernel_launch(void* const* d_in, const int* in_sizes, int n_in,
                              void* d_out, int out_size)
{
    const float* x  = (const float*)d_in[0];
    const float* Wq = (const float*)d_in[1];
    const float* bq = (const float*)d_in[2];
    const float* Wk = (const float*)d_in[3];
    const float* bk = (const float*)d_in[4];
    const float* Wv = (const float*)d_in[5];
    const float* bv = (const float*)d_in[6];
    const float* Wo = (const float*)d_in[7];
    const float* bo = (const float*)d_in[8];
    float* out = (float*)d_out;

    (void)in_sizes; (void)n_in; (void)out_size;

    cudaFuncSetAttribute(gemm_qkv_kernel,
                         cudaFuncAttributeMaxDynamicSharedMemorySize, GEMMQ_SMEM_BYTES);
    cudaFuncSetAttribute(gemm_proj_kernel,
                         cudaFuncAttributeMaxDynamicSharedMemorySize, GEMM64_SMEM_BYTES);
    cudaFuncSetAttribute(attn_mma_kernel,
                         cudaFuncAttributeMaxDynamicSharedMemorySize, ATN_SMEM_BYTES);

    prep_kernel<<<dim3(16, 16, 12), 256>>>(x, Wq, Wk, Wv, Wo);
    gemm_qkv_kernel<<<dim3(32, 24), 128, GEMMQ_SMEM_BYTES>>>(bq, bk, bv);
    attn_mma_kernel<<<dim3(64, NH), 128, ATN_SMEM_BYTES>>>();
    attn_combine_kernel<<<4096, 256>>>();
    gemm_proj_kernel<<<dim3(32, 8), 256, GEMM64_SMEM_BYTES>>>(bo, out);
}

// round 16
// speedup vs baseline: 1.5236x; 1.4270x over previous
#include <cuda_runtime.h>
#include <cuda_fp16.h>
#include <cstdint>
#include <math.h>

#define S_LEN 2048
#define E_DIM 1024
#define NH    16
#define DH    64

// ---------------------------------------------------------------------------
// Scratch (__device__ globals; allocation-free rule)
// q: fp16 hi+lo (A operand of QK^T, pre-scaled 0.125). k/v: single fp16 (B ops).
// ---------------------------------------------------------------------------
__device__ __align__(16) __half g_qh[NH * S_LEN * DH];
__device__ __align__(16) __half g_ql[NH * S_LEN * DH];
__device__ __align__(16) __half g_k16[NH * S_LEN * DH];
__device__ __align__(16) __half g_v16[NH * S_LEN * DH];

__device__ __align__(16) __half g_xh[S_LEN * E_DIM];
__device__ __align__(16) __half g_xl[S_LEN * E_DIM];
__device__ __align__(16) __half g_wt16[3 * E_DIM * E_DIM];   // [3072][1024] K-major
__device__ __align__(16) __half g_wot16[E_DIM * E_DIM];      // [1024][1024] K-major
__device__ __align__(16) __half g_aoh[S_LEN * E_DIM];        // attn out, concat layout
__device__ __align__(16) __half g_aol[S_LEN * E_DIM];

// split-KV partials
__device__ __align__(16) float g_opart[2 * NH * S_LEN * DH];
__device__ __align__(16) float g_mpart[2 * NH * S_LEN];
__device__ __align__(16) float g_lpart[2 * NH * S_LEN];

// ---------------------------------------------------------------------------
// Baseline-PTX helpers
// ---------------------------------------------------------------------------
__device__ __forceinline__ uint32_t smem_to_u32(const void* p) {
    uint32_t a;
    asm("{ .reg .u64 t; cvta.to.shared.u64 t, %1; cvt.u32.u64 %0, t; }"
        : "=r"(a) : "l"(p));
    return a;
}

__device__ __forceinline__ void ldsm4(uint32_t* r, uint32_t addr) {
    asm volatile("ldmatrix.sync.aligned.m8n8.x4.shared.b16 {%0,%1,%2,%3}, [%4];"
        : "=r"(r[0]), "=r"(r[1]), "=r"(r[2]), "=r"(r[3]) : "r"(addr));
}
__device__ __forceinline__ void ldsm4t(uint32_t* r, uint32_t addr) {
    asm volatile("ldmatrix.sync.aligned.m8n8.x4.trans.shared.b16 {%0,%1,%2,%3}, [%4];"
        : "=r"(r[0]), "=r"(r[1]), "=r"(r[2]), "=r"(r[3]) : "r"(addr));
}

__device__ __forceinline__ void mma16816h(float* c, const uint32_t* a, const uint32_t* b) {
    asm volatile(
        "mma.sync.aligned.m16n8k16.row.col.f32.f16.f16.f32 "
        "{%0,%1,%2,%3}, {%4,%5,%6,%7}, {%8,%9}, {%0,%1,%2,%3};"
        : "+f"(c[0]), "+f"(c[1]), "+f"(c[2]), "+f"(c[3])
        : "r"(a[0]), "r"(a[1]), "r"(a[2]), "r"(a[3]), "r"(b[0]), "r"(b[1]));
}

__device__ __forceinline__ void cpasync16(uint32_t saddr, const void* gaddr) {
    asm volatile("cp.async.cg.shared.global [%0], [%1], 16;"
        :: "r"(saddr), "l"(gaddr) : "memory");
}
#define CP_COMMIT() asm volatile("cp.async.commit_group;" ::: "memory")
#define CP_WAIT(n)  asm volatile("cp.async.wait_group %0;" :: "n"(n) : "memory")

// fp16 split helpers
__device__ __forceinline__ void splith2(float a, float b, __half* ph, __half* pl) {
    __half2 h, l;
    h.x = __float2half(a); h.y = __float2half(b);
    l.x = __float2half(a - __half2float(h.x));
    l.y = __float2half(b - __half2float(h.y));
    *(__half2*)ph = h; *(__half2*)pl = l;
}
__device__ __forceinline__ void storeh2(float a, float b, __half* p) {
    __half2 h;
    h.x = __float2half(a); h.y = __float2half(b);
    *(__half2*)p = h;
}
__device__ __forceinline__ void packsplit2h(float a, float b, uint32_t& hi, uint32_t& lo) {
    __half2 h, l;
    h.x = __float2half(a); h.y = __float2half(b);
    l.x = __float2half(a - __half2float(h.x));
    l.y = __float2half(b - __half2float(h.y));
    hi = *(uint32_t*)&h; lo = *(uint32_t*)&l;
}

// swizzled byte offset, 64B rows (4x16B chunks)
__device__ __forceinline__ uint32_t swz(uint32_t row, uint32_t chunk) {
    return row * 64 + ((chunk ^ ((row >> 1) & 3)) << 4);
}
// swizzled byte offset, 128B rows (8x16B chunks)
__device__ __forceinline__ uint32_t swz8(uint32_t row, uint32_t chunk) {
    return row * 128 + ((chunk ^ (row & 7)) << 4);
}

// ---------------------------------------------------------------------------
// Merged prologue: z<3 Wqkv->fp16, z==3 Wo->fp16, z>=4 x split. grid(16,16,12)
// ---------------------------------------------------------------------------
__global__ __launch_bounds__(256) void prep_kernel(
    const float* __restrict__ x,
    const float* __restrict__ Wq, const float* __restrict__ Wk,
    const float* __restrict__ Wv, const float* __restrict__ Wo)
{
    const int z = blockIdx.z;
    const int tid = threadIdx.x;

    if (z < 3) {
        __shared__ float s[64][65];
        const int h = blockIdx.y, e0 = blockIdx.x * 64;
        const float* W = (z == 0 ? Wq : z == 1 ? Wk : Wv) + (size_t)h * E_DIM * DH;
        #pragma unroll
        for (int i = 0; i < 16; i++) {
            int idx = tid + i * 256;
            int e = idx >> 6, d = idx & 63;
            s[d][e] = W[(size_t)(e0 + e) * DH + d];
        }
        __syncthreads();
        const int nb = z * 1024 + h * 64;
        #pragma unroll
        for (int i = 0; i < 16; i++) {
            int idx = tid + i * 256;
            int d = idx >> 6, e = idx & 63;
            g_wt16[(size_t)(nb + d) * E_DIM + e0 + e] = __float2half(s[d][e]);
        }
    } else if (z == 3) {
        __shared__ float s[64][65];
        const int f0 = blockIdx.x * 64, e0 = blockIdx.y * 64;
        #pragma unroll
        for (int i = 0; i < 16; i++) {
            int idx = tid + i * 256;
            int fl = idx >> 6, el = idx & 63;
            s[el][fl] = Wo[(size_t)(f0 + fl) * E_DIM + e0 + el];
        }
        __syncthreads();
        #pragma unroll
        for (int i = 0; i < 16; i++) {
            int idx = tid + i * 256;
            int el = idx >> 6, fl = idx & 63;
            g_wot16[(size_t)(e0 + el) * E_DIM + f0 + fl] = __float2half(s[el][fl]);
        }
    } else {
        const int lb = (z - 4) * 256 + blockIdx.y * 16 + blockIdx.x;
        int i = (lb * 256 + tid) * 4;
        float4 v = *(const float4*)(x + i);
        splith2(v.x, v.y, g_xh + i, g_xl + i);
        splith2(v.z, v.w, g_xh + i + 2, g_xl + i + 2);
    }
}

// ---------------------------------------------------------------------------
// QKV GEMM: BM=64 / BN=128, 128 threads, 3 CTAs/SM, fp16 2-term (A split).
// stage = Ah(4K)+Al(4K)+B(8K) = 16KB; 3 stages = 48KB. grid (32, 24).
// ---------------------------------------------------------------------------
#define STGQ_B 16384
#define GEMMQ_SMEM_BYTES (3 * STGQ_B)

__global__ __launch_bounds__(128, 3) void gemm_qkv_kernel(
    const float* __restrict__ bias0, const float* __restrict__ bias1,
    const float* __restrict__ bias2)
{
    extern __shared__ __half gsq[];
    const uint32_t sb = smem_to_u32(gsq);
    const int tid = threadIdx.x;
    const int wid = tid >> 5, lane = tid & 31;
    const int wn = wid;
    const int m0 = blockIdx.x * 64, n0 = blockIdx.y * 128;

    const __half* pAh = g_xh + (size_t)m0 * E_DIM;
    const __half* pAl = g_xl + (size_t)m0 * E_DIM;
    const __half* pB  = g_wt16 + (size_t)n0 * E_DIM;

    auto issue = [&](int s, int kc) {
        const int k0 = kc * 32;
        const uint32_t stb = sb + s * STGQ_B;
        #pragma unroll
        for (int i = 0; i < 2; i++) {     // A: 64 rows x 4 chunks = 256 items each
            int idx = tid + i * 128;
            uint32_t row = idx >> 2, q = idx & 3;
            cpasync16(stb + swz(row, q), pAh + (size_t)row * E_DIM + k0 + q * 8);
            cpasync16(stb + 4096 + swz(row, q), pAl + (size_t)row * E_DIM + k0 + q * 8);
        }
        #pragma unroll
        for (int i = 0; i < 4; i++) {     // B: 128 rows x 4 chunks = 512 items
            int idx = tid + i * 128;
            uint32_t row = idx >> 2, q = idx & 3;
            cpasync16(stb + 8192 + swz(row, q), pB + (size_t)row * E_DIM + k0 + q * 8);
        }
    };

    float c[4][4][4];
    #pragma unroll
    for (int mi = 0; mi < 4; mi++)
        #pragma unroll
        for (int ni = 0; ni < 4; ni++)
            #pragma unroll
            for (int e = 0; e < 4; e++) c[mi][ni][e] = 0.f;

    const uint32_t aRow = lane & 15;
    const uint32_t aCh = lane >> 4;
    const uint32_t bGrp = lane >> 3, bRin = lane & 7;
    const uint32_t bRowBase = wn * 32 + ((bGrp >> 1) << 3) + bRin;
    const uint32_t bCh = bGrp & 1;

    issue(0, 0); CP_COMMIT();
    issue(1, 1); CP_COMMIT();

    for (int kc = 0; kc < 32; kc++) {
        const int buf = kc % 3;
        if (kc < 31) { CP_WAIT(1); } else { CP_WAIT(0); }
        __syncthreads();
        if (kc + 2 < 32) { issue((kc + 2) % 3, kc + 2); CP_COMMIT(); }

        const uint32_t saH = sb + buf * STGQ_B;
        const uint32_t saL = saH + 4096;
        const uint32_t sB  = saH + 8192;

        #pragma unroll
        for (int ks = 0; ks < 2; ks++) {
            uint32_t ah[4][4], al[4][4], bfr[4][2];
            #pragma unroll
            for (int mi = 0; mi < 4; mi++) {
                uint32_t off = swz(aRow + mi * 16, ks * 2 + aCh);
                ldsm4(ah[mi], saH + off);
                ldsm4(al[mi], saL + off);
            }
            #pragma unroll
            for (int half = 0; half < 2; half++) {
                uint32_t off = swz(bRowBase + half * 16, ks * 2 + bCh);
                ldsm4(&bfr[half * 2][0], sB + off);
            }
            #pragma unroll
            for (int mi = 0; mi < 4; mi++)
                #pragma unroll
                for (int ni = 0; ni < 4; ni++) {
                    mma16816h(c[mi][ni], ah[mi], bfr[ni]);
                    mma16816h(c[mi][ni], al[mi], bfr[ni]);
                }
        }
    }

    const int rBase = m0 + (lane >> 2);
    const int nBase = n0 + wn * 32 + (lane & 3) * 2;
    #pragma unroll
    for (int mi = 0; mi < 4; mi++) {
        #pragma unroll
        for (int ni = 0; ni < 4; ni++) {
            int n = nBase + ni * 8;
            #pragma unroll
            for (int half = 0; half < 2; half++) {
                int row = rBase + mi * 16 + half * 8;
                float v0 = c[mi][ni][half * 2 + 0];
                float v1 = c[mi][ni][half * 2 + 1];
                const int z = n >> 10;
                const float* bias = z == 0 ? bias0 : z == 1 ? bias1 : bias2;
                const int h = (n >> 6) & 15, d = n & 63, bi = n & 1023;
                size_t o = ((size_t)h * S_LEN + row) * DH + d;
                if (z == 0) {
                    float a = (v0 + __ldg(&bias[bi + 0])) * 0.125f;
                    float b = (v1 + __ldg(&bias[bi + 1])) * 0.125f;
                    splith2(a, b, g_qh + o, g_ql + o);
                } else {
                    float a = v0 + __ldg(&bias[bi + 0]);
                    float b = v1 + __ldg(&bias[bi + 1]);
                    storeh2(a, b, (z == 1 ? g_k16 : g_v16) + o);
                }
            }
        }
    }
}

// ---------------------------------------------------------------------------
// Proj GEMM: BM=64 / BN=128, 256 threads, fp16 2-term; grid (32, 8).
// stage = Ah(4K)+Al(4K)+B(8K) = 16KB; 3 stages = 48KB.
// ---------------------------------------------------------------------------
#define STGP_B 16384
#define GEMMP_SMEM_BYTES (3 * STGP_B)

__global__ __launch_bounds__(256, 2) void gemm_proj_kernel(
    const float* __restrict__ bo, float* __restrict__ out)
{
    extern __shared__ __half gs2[];
    const uint32_t sb = smem_to_u32(gs2);
    const int tid = threadIdx.x;
    const int wid = tid >> 5, lane = tid & 31;
    const int wm = wid >> 2, wn = wid & 3;
    const int m0 = blockIdx.x * 64, n0 = blockIdx.y * 128;

    const __half* pAh = g_aoh + (size_t)m0 * E_DIM;
    const __half* pAl = g_aol + (size_t)m0 * E_DIM;
    const __half* pB  = g_wot16 + (size_t)n0 * E_DIM;

    auto issue = [&](int s, int kc) {
        const int k0 = kc * 32;
        const uint32_t stb = sb + s * STGP_B;
        {
            uint32_t row = tid >> 2, q = tid & 3;
            cpasync16(stb + swz(row, q), pAh + (size_t)row * E_DIM + k0 + q * 8);
            cpasync16(stb + 4096 + swz(row, q), pAl + (size_t)row * E_DIM + k0 + q * 8);
        }
        #pragma unroll
        for (int i = 0; i < 2; i++) {
            int idx = tid + i * 256;
            uint32_t row = idx >> 2, q = idx & 3;
            cpasync16(stb + 8192 + swz(row, q), pB + (size_t)row * E_DIM + k0 + q * 8);
        }
    };

    float c[2][4][4];
    #pragma unroll
    for (int mi = 0; mi < 2; mi++)
        #pragma unroll
        for (int ni = 0; ni < 4; ni++)
            #pragma unroll
            for (int e = 0; e < 4; e++) c[mi][ni][e] = 0.f;

    const uint32_t aRow = wm * 32 + (lane & 15);
    const uint32_t aCh = lane >> 4;
    const uint32_t bGrp = lane >> 3, bRin = lane & 7;
    const uint32_t bRowBase = wn * 32 + ((bGrp >> 1) << 3) + bRin;
    const uint32_t bCh = bGrp & 1;

    issue(0, 0); CP_COMMIT();
    issue(1, 1); CP_COMMIT();

    for (int kc = 0; kc < 32; kc++) {
        const int buf = kc % 3;
        if (kc < 31) { CP_WAIT(1); } else { CP_WAIT(0); }
        __syncthreads();
        if (kc + 2 < 32) { issue((kc + 2) % 3, kc + 2); CP_COMMIT(); }

        const uint32_t saH = sb + buf * STGP_B;
        const uint32_t saL = saH + 4096;
        const uint32_t sB  = saH + 8192;

        #pragma unroll
        for (int ks = 0; ks < 2; ks++) {
            uint32_t ah[2][4], al[2][4], bfr[4][2];
            #pragma unroll
            for (int mi = 0; mi < 2; mi++) {
                uint32_t off = swz(aRow + mi * 16, ks * 2 + aCh);
                ldsm4(ah[mi], saH + off);
                ldsm4(al[mi], saL + off);
            }
            #pragma unroll
            for (int half = 0; half < 2; half++) {
                uint32_t off = swz(bRowBase + half * 16, ks * 2 + bCh);
                ldsm4(&bfr[half * 2][0], sB + off);
            }
            #pragma unroll
            for (int mi = 0; mi < 2; mi++)
                #pragma unroll
                for (int ni = 0; ni < 4; ni++) {
                    mma16816h(c[mi][ni], ah[mi], bfr[ni]);
                    mma16816h(c[mi][ni], al[mi], bfr[ni]);
                }
        }
    }

    const int rBase = m0 + wm * 32 + (lane >> 2);
    const int nBase = n0 + wn * 32 + (lane & 3) * 2;
    #pragma unroll
    for (int mi = 0; mi < 2; mi++) {
        #pragma unroll
        for (int ni = 0; ni < 4; ni++) {
            int n = nBase + ni * 8;
            #pragma unroll
            for (int half = 0; half < 2; half++) {
                int row = rBase + mi * 16 + half * 8;
                float2 o;
                o.x = c[mi][ni][half * 2 + 0] + __ldg(&bo[n + 0]);
                o.y = c[mi][ni][half * 2 + 1] + __ldg(&bo[n + 1]);
                *(float2*)&out[(size_t)row * E_DIM + n] = o;
            }
        }
    }
}

// ---------------------------------------------------------------------------
// Split-KV tensor-core causal flash attention, fp16 2-term.
// K/V single fp16: stage = K(8K)+V(8K) = 16KB; 2 stages = 32KB. 3 CTAs/SM.
// ---------------------------------------------------------------------------
#define KV_TILE_B  8192
#define KV_STAGE_B 16384
#define ATN_SMEM_BYTES (2 * KV_STAGE_B)   // 32768

__global__ __launch_bounds__(128, 3) void attn_mma_kernel()
{
    extern __shared__ __half as2[];
    const uint32_t sbq = smem_to_u32(as2);
    const int tid = threadIdx.x, lane = tid & 31, w = tid >> 5;
    const int i0    = ((int)gridDim.x >> 1) - 1 - ((int)blockIdx.x >> 1);
    const int split = blockIdx.x & 1;
    const int h = blockIdx.y;

    const int total = i0 + 1;
    const int half  = (total + 1) >> 1;
    const int jb = split ? half : 0;
    const int je = split ? total : half;

    const int rowq = lane >> 2, colq = (lane & 3) * 2;
    const size_t pbase = ((size_t)(split * NH + h) * S_LEN) + i0 * 64;

    if (jb >= je) {
        const int r0 = w * 16 + rowq;
        #pragma unroll
        for (int ni = 0; ni < 8; ni++) {
            const int col = colq + ni * 8;
            float2 z2 = make_float2(0.f, 0.f);
            *(float2*)&g_opart[(pbase + r0) * DH + col] = z2;
            *(float2*)&g_opart[(pbase + r0 + 8) * DH + col] = z2;
        }
        if ((lane & 3) == 0) {
            g_mpart[pbase + r0] = -1e30f;
            g_mpart[pbase + r0 + 8] = -1e30f;
            g_lpart[pbase + r0] = 0.f;
            g_lpart[pbase + r0 + 8] = 0.f;
        }
        return;
    }

    auto load_kv = [&](int s, int jt) {
        const size_t gofs = ((size_t)h * S_LEN + jt * 64) * DH;
        const __half* srcK = g_k16 + gofs;
        const __half* srcV = g_v16 + gofs;
        const uint32_t stb = sbq + s * KV_STAGE_B;
        #pragma unroll
        for (int i = 0; i < 4; i++) {
            int idx = tid + i * 128;
            uint32_t row = idx >> 3, q = idx & 7;
            cpasync16(stb + swz8(row, q), srcK + row * 64 + q * 8);
            cpasync16(stb + KV_TILE_B + swz8(row, q), srcV + row * 64 + q * 8);
        }
    };

    load_kv(0, jb);
    CP_COMMIT();

    const __half* Qh = g_qh + ((size_t)h * S_LEN + i0 * 64) * DH;
    const __half* Ql = g_ql + ((size_t)h * S_LEN + i0 * 64) * DH;
    uint32_t aQh[4][4], aQl[4][4];
    {
        const int qr = w * 16 + rowq;
        const int qc = colq;
        #pragma unroll
        for (int ks = 0; ks < 4; ks++) {
            const __half* ph = Qh + (size_t)qr * DH + ks * 16 + qc;
            const __half* pl = Ql + (size_t)qr * DH + ks * 16 + qc;
            aQh[ks][0] = *(const uint32_t*)(ph);
            aQh[ks][1] = *(const uint32_t*)(ph + 8 * DH);
            aQh[ks][2] = *(const uint32_t*)(ph + 8);
            aQh[ks][3] = *(const uint32_t*)(ph + 8 * DH + 8);
            aQl[ks][0] = *(const uint32_t*)(pl);
            aQl[ks][1] = *(const uint32_t*)(pl + 8 * DH);
            aQl[ks][2] = *(const uint32_t*)(pl + 8);
            aQl[ks][3] = *(const uint32_t*)(pl + 8 * DH + 8);
        }
    }

    float m0 = -1e30f, m1 = -1e30f, l0 = 0.f, l1 = 0.f;
    float oc[8][4];
    #pragma unroll
    for (int ni = 0; ni < 8; ni++)
        #pragma unroll
        for (int e = 0; e < 4; e++) oc[ni][e] = 0.f;

    const int grp = lane >> 3, rin = lane & 7;

    for (int jt = jb; jt < je; jt++) {
        const int buf = (jt - jb) & 1;
        CP_WAIT(0);
        __syncthreads();
        if (jt + 1 < je) { load_kv(buf ^ 1, jt + 1); CP_COMMIT(); }

        const uint32_t stb = sbq + buf * KV_STAGE_B;
        const uint32_t sK = stb, sV = stb + KV_TILE_B;

        // ---- S = Q K^T ----
        float sc[8][4];
        #pragma unroll
        for (int ni = 0; ni < 8; ni++)
            #pragma unroll
            for (int e = 0; e < 4; e++) sc[ni][e] = 0.f;

        #pragma unroll
        for (int ks = 0; ks < 4; ks++) {
            #pragma unroll
            for (int g = 0; g < 4; g++) {
                uint32_t kfr[4];
                uint32_t off = swz8(g * 16 + ((grp >> 1) << 3) + rin,
                                    ks * 2 + (grp & 1));
                ldsm4(kfr, sK + off);
                mma16816h(sc[2 * g],     aQh[ks], kfr);
                mma16816h(sc[2 * g],     aQl[ks], kfr);
                mma16816h(sc[2 * g + 1], aQh[ks], kfr + 2);
                mma16816h(sc[2 * g + 1], aQl[ks], kfr + 2);
            }
        }

        // ---- causal mask (diagonal tile only) ----
        if (jt == i0) {
            const int rowL0 = w * 16 + rowq, rowL1 = rowL0 + 8;
            #pragma unroll
            for (int ni = 0; ni < 8; ni++) {
                int colL = ni * 8 + colq;
                if (colL     > rowL0) sc[ni][0] = -1e30f;
                if (colL + 1 > rowL0) sc[ni][1] = -1e30f;
                if (colL     > rowL1) sc[ni][2] = -1e30f;
                if (colL + 1 > rowL1) sc[ni][3] = -1e30f;
            }
        }

        // ---- online softmax ----
        float t0 = -1e30f, t1 = -1e30f;
        #pragma unroll
        for (int ni = 0; ni < 8; ni++) {
            t0 = fmaxf(t0, fmaxf(sc[ni][0], sc[ni][1]));
            t1 = fmaxf(t1, fmaxf(sc[ni][2], sc[ni][3]));
        }
        t0 = fmaxf(t0, __shfl_xor_sync(0xffffffffu, t0, 1));
        t0 = fmaxf(t0, __shfl_xor_sync(0xffffffffu, t0, 2));
        t1 = fmaxf(t1, __shfl_xor_sync(0xffffffffu, t1, 1));
        t1 = fmaxf(t1, __shfl_xor_sync(0xffffffffu, t1, 2));
        const float m0n = fmaxf(m0, t0), m1n = fmaxf(m1, t1);
        const float f0 = __expf(m0 - m0n), f1 = __expf(m1 - m1n);

        float rs0 = 0.f, rs1 = 0.f;
        #pragma unroll
        for (int ni = 0; ni < 8; ni++) {
            sc[ni][0] = __expf(sc[ni][0] - m0n); rs0 += sc[ni][0];
            sc[ni][1] = __expf(sc[ni][1] - m0n); rs0 += sc[ni][1];
            sc[ni][2] = __expf(sc[ni][2] - m1n); rs1 += sc[ni][2];
            sc[ni][3] = __expf(sc[ni][3] - m1n); rs1 += sc[ni][3];
        }
        rs0 += __shfl_xor_sync(0xffffffffu, rs0, 1);
        rs0 += __shfl_xor_sync(0xffffffffu, rs0, 2);
        rs1 += __shfl_xor_sync(0xffffffffu, rs1, 1);
        rs1 += __shfl_xor_sync(0xffffffffu, rs1, 2);
        l0 = l0 * f0 + rs0; l1 = l1 * f1 + rs1;
        m0 = m0n; m1 = m1n;
        #pragma unroll
        for (int ni = 0; ni < 8; ni++) {
            oc[ni][0] *= f0; oc[ni][1] *= f0;
            oc[ni][2] *= f1; oc[ni][3] *= f1;
        }

        // ---- pack P fragments (fp16 hi/lo) ----
        uint32_t aPh[4][4], aPl[4][4];
        #pragma unroll
        for (int ks = 0; ks < 4; ks++) {
            const int ta = 2 * ks, tb = 2 * ks + 1;
            packsplit2h(sc[ta][0], sc[ta][1], aPh[ks][0], aPl[ks][0]);
            packsplit2h(sc[ta][2], sc[ta][3], aPh[ks][1], aPl[ks][1]);
            packsplit2h(sc[tb][0], sc[tb][1], aPh[ks][2], aPl[ks][2]);
            packsplit2h(sc[tb][2], sc[tb][3], aPh[ks][3], aPl[ks][3]);
        }

        // ---- O += P V ----
        #pragma unroll
        for (int ks = 0; ks < 4; ks++) {
            #pragma unroll
            for (int g = 0; g < 4; g++) {
                uint32_t vfr[4];
                uint32_t off = swz8(ks * 16 + ((grp & 1) << 3) + rin,
                                    g * 2 + (grp >> 1));
                ldsm4t(vfr, sV + off);
                mma16816h(oc[2 * g],     aPh[ks], vfr);
                mma16816h(oc[2 * g],     aPl[ks], vfr);
                mma16816h(oc[2 * g + 1], aPh[ks], vfr + 2);
                mma16816h(oc[2 * g + 1], aPl[ks], vfr + 2);
            }
        }
    }

    const int r0 = w * 16 + rowq;
    #pragma unroll
    for (int ni = 0; ni < 8; ni++) {
        const int col = colq + ni * 8;
        *(float2*)&g_opart[(pbase + r0) * DH + col] =
            make_float2(oc[ni][0], oc[ni][1]);
        *(float2*)&g_opart[(pbase + r0 + 8) * DH + col] =
            make_float2(oc[ni][2], oc[ni][3]);
    }
    if ((lane & 3) == 0) {
        g_mpart[pbase + r0] = m0;     g_lpart[pbase + r0] = l0;
        g_mpart[pbase + r0 + 8] = m1; g_lpart[pbase + r0 + 8] = l1;
    }
}

// ---------------------------------------------------------------------------
// Combine partials -> g_aoh/g_aol (fp16 hi/lo). grid = 4096 x 256.
// ---------------------------------------------------------------------------
__global__ __launch_bounds__(256) void attn_combine_kernel()
{
    const int idx = blockIdx.x * 256 + threadIdx.x;
    const int hrow = idx >> 5;
    const int d2 = (idx & 31) * 2;
    const int row = hrow & (S_LEN - 1);
    const int h = hrow >> 11;

    const float m0 = __ldg(&g_mpart[hrow]);
    const float m1 = __ldg(&g_mpart[NH * S_LEN + hrow]);
    const float l0 = __ldg(&g_lpart[hrow]);
    const float l1 = __ldg(&g_lpart[NH * S_LEN + hrow]);
    const float M = fmaxf(m0, m1);
    const float e0 = __expf(m0 - M), e1 = __expf(m1 - M);
    const float inv = 1.f / (l0 * e0 + l1 * e1);

    float2 O0 = *(const float2*)&g_opart[(size_t)hrow * DH + d2];
    float2 O1 = *(const float2*)&g_opart[(size_t)(NH * S_LEN + hrow) * DH + d2];
    float a = (O0.x * e0 + O1.x * e1) * inv;
    float b = (O0.y * e0 + O1.y * e1) * inv;

    size_t o = (size_t)row * E_DIM + h * DH + d2;
    splith2(a, b, g_aoh + o, g_aol + o);
}

// ---------------------------------------------------------------------------
extern "C" void kernel_launch(void* const* d_in, const int* in_sizes, int n_in,
                              void* d_out, int out_size)
{
    const float* x  = (const float*)d_in[0];
    const float* Wq = (const float*)d_in[1];
    const float* bq = (const float*)d_in[2];
    const float* Wk = (const float*)d_in[3];
    const float* bk = (const float*)d_in[4];
    const float* Wv = (const float*)d_in[5];
    const float* bv = (const float*)d_in[6];
    const float* Wo = (const float*)d_in[7];
    const float* bo = (const float*)d_in[8];
    float* out = (float*)d_out;

    (void)in_sizes; (void)n_in; (void)out_size;

    cudaFuncSetAttribute(gemm_qkv_kernel,
                         cudaFuncAttributeMaxDynamicSharedMemorySize, GEMMQ_SMEM_BYTES);
    cudaFuncSetAttribute(gemm_proj_kernel,
                         cudaFuncAttributeMaxDynamicSharedMemorySize, GEMMP_SMEM_BYTES);
    cudaFuncSetAttribute(attn_mma_kernel,
                         cudaFuncAttributeMaxDynamicSharedMemorySize, ATN_SMEM_BYTES);

    prep_kernel<<<dim3(16, 16, 12), 256>>>(x, Wq, Wk, Wv, Wo);
    gemm_qkv_kernel<<<dim3(32, 24), 128, GEMMQ_SMEM_BYTES>>>(bq, bk, bv);
    attn_mma_kernel<<<dim3(64, NH), 128, ATN_SMEM_BYTES>>>();
    attn_combine_kernel<<<4096, 256>>>();
    gemm_proj_kernel<<<dim3(32, 8), 256, GEMMP_SMEM_BYTES>>>(bo, out);
}

// round 17
// speedup vs baseline: 1.7119x; 1.1236x over previous
#include <cuda_runtime.h>
#include <cuda_fp16.h>
#include <cstdint>
#include <math.h>

#define S_LEN 2048
#define E_DIM 1024
#define NH    16
#define DH    64

// ---------------------------------------------------------------------------
// Scratch (__device__ globals; allocation-free rule)
// ---------------------------------------------------------------------------
__device__ __align__(16) __half g_qh[NH * S_LEN * DH];
__device__ __align__(16) __half g_ql[NH * S_LEN * DH];
__device__ __align__(16) __half g_k16[NH * S_LEN * DH];
__device__ __align__(16) __half g_v16[NH * S_LEN * DH];

__device__ __align__(16) __half g_xh[S_LEN * E_DIM];
__device__ __align__(16) __half g_xl[S_LEN * E_DIM];
__device__ __align__(16) __half g_wt16[3 * E_DIM * E_DIM];   // [3072][1024] K-major
__device__ __align__(16) __half g_wot16[E_DIM * E_DIM];      // [1024][1024] K-major
__device__ __align__(16) __half g_ao16[S_LEN * E_DIM];       // attn out, concat, single fp16

// split-KV partials
__device__ __align__(16) float g_opart[2 * NH * S_LEN * DH];
__device__ __align__(16) float g_mpart[2 * NH * S_LEN];
__device__ __align__(16) float g_lpart[2 * NH * S_LEN];

// ---------------------------------------------------------------------------
// Baseline-PTX helpers
// ---------------------------------------------------------------------------
__device__ __forceinline__ uint32_t smem_to_u32(const void* p) {
    uint32_t a;
    asm("{ .reg .u64 t; cvta.to.shared.u64 t, %1; cvt.u32.u64 %0, t; }"
        : "=r"(a) : "l"(p));
    return a;
}

__device__ __forceinline__ void ldsm4(uint32_t* r, uint32_t addr) {
    asm volatile("ldmatrix.sync.aligned.m8n8.x4.shared.b16 {%0,%1,%2,%3}, [%4];"
        : "=r"(r[0]), "=r"(r[1]), "=r"(r[2]), "=r"(r[3]) : "r"(addr));
}
__device__ __forceinline__ void ldsm4t(uint32_t* r, uint32_t addr) {
    asm volatile("ldmatrix.sync.aligned.m8n8.x4.trans.shared.b16 {%0,%1,%2,%3}, [%4];"
        : "=r"(r[0]), "=r"(r[1]), "=r"(r[2]), "=r"(r[3]) : "r"(addr));
}

__device__ __forceinline__ void mma16816h(float* c, const uint32_t* a, const uint32_t* b) {
    asm volatile(
        "mma.sync.aligned.m16n8k16.row.col.f32.f16.f16.f32 "
        "{%0,%1,%2,%3}, {%4,%5,%6,%7}, {%8,%9}, {%0,%1,%2,%3};"
        : "+f"(c[0]), "+f"(c[1]), "+f"(c[2]), "+f"(c[3])
        : "r"(a[0]), "r"(a[1]), "r"(a[2]), "r"(a[3]), "r"(b[0]), "r"(b[1]));
}

__device__ __forceinline__ void cpasync16(uint32_t saddr, const void* gaddr) {
    asm volatile("cp.async.cg.shared.global [%0], [%1], 16;"
        :: "r"(saddr), "l"(gaddr) : "memory");
}
#define CP_COMMIT() asm volatile("cp.async.commit_group;" ::: "memory")
#define CP_WAIT(n)  asm volatile("cp.async.wait_group %0;" :: "n"(n) : "memory")

// fp16 helpers
__device__ __forceinline__ void splith2(float a, float b, __half* ph, __half* pl) {
    __half2 h, l;
    h.x = __float2half(a); h.y = __float2half(b);
    l.x = __float2half(a - __half2float(h.x));
    l.y = __float2half(b - __half2float(h.y));
    *(__half2*)ph = h; *(__half2*)pl = l;
}
__device__ __forceinline__ void storeh2(float a, float b, __half* p) {
    __half2 h;
    h.x = __float2half(a); h.y = __float2half(b);
    *(__half2*)p = h;
}
__device__ __forceinline__ uint32_t packh2(float a, float b) {
    __half2 h;
    h.x = __float2half(a); h.y = __float2half(b);
    return *(uint32_t*)&h;
}

// swizzled byte offset, 64B rows (4x16B chunks)
__device__ __forceinline__ uint32_t swz(uint32_t row, uint32_t chunk) {
    return row * 64 + ((chunk ^ ((row >> 1) & 3)) << 4);
}
// swizzled byte offset, 128B rows (8x16B chunks)
__device__ __forceinline__ uint32_t swz8(uint32_t row, uint32_t chunk) {
    return row * 128 + ((chunk ^ (row & 7)) << 4);
}

// ---------------------------------------------------------------------------
// Merged prologue: z<3 Wqkv->fp16, z==3 Wo->fp16, z>=4 x split. grid(16,16,12)
// ---------------------------------------------------------------------------
__global__ __launch_bounds__(256) void prep_kernel(
    const float* __restrict__ x,
    const float* __restrict__ Wq, const float* __restrict__ Wk,
    const float* __restrict__ Wv, const float* __restrict__ Wo)
{
    const int z = blockIdx.z;
    const int tid = threadIdx.x;

    if (z < 3) {
        __shared__ float s[64][65];
        const int h = blockIdx.y, e0 = blockIdx.x * 64;
        const float* W = (z == 0 ? Wq : z == 1 ? Wk : Wv) + (size_t)h * E_DIM * DH;
        #pragma unroll
        for (int i = 0; i < 16; i++) {
            int idx = tid + i * 256;
            int e = idx >> 6, d = idx & 63;
            s[d][e] = W[(size_t)(e0 + e) * DH + d];
        }
        __syncthreads();
        const int nb = z * 1024 + h * 64;
        #pragma unroll
        for (int i = 0; i < 16; i++) {
            int idx = tid + i * 256;
            int d = idx >> 6, e = idx & 63;
            g_wt16[(size_t)(nb + d) * E_DIM + e0 + e] = __float2half(s[d][e]);
        }
    } else if (z == 3) {
        __shared__ float s[64][65];
        const int f0 = blockIdx.x * 64, e0 = blockIdx.y * 64;
        #pragma unroll
        for (int i = 0; i < 16; i++) {
            int idx = tid + i * 256;
            int fl = idx >> 6, el = idx & 63;
            s[el][fl] = Wo[(size_t)(f0 + fl) * E_DIM + e0 + el];
        }
        __syncthreads();
        #pragma unroll
        for (int i = 0; i < 16; i++) {
            int idx = tid + i * 256;
            int el = idx >> 6, fl = idx & 63;
            g_wot16[(size_t)(e0 + el) * E_DIM + f0 + fl] = __float2half(s[el][fl]);
        }
    } else {
        const int lb = (z - 4) * 256 + blockIdx.y * 16 + blockIdx.x;
        int i = (lb * 256 + tid) * 4;
        float4 v = *(const float4*)(x + i);
        splith2(v.x, v.y, g_xh + i, g_xl + i);
        splith2(v.z, v.w, g_xh + i + 2, g_xl + i + 2);
    }
}

// ---------------------------------------------------------------------------
// QKV GEMM: BM=64 / BN=128, 128 threads, 3 CTAs/SM, fp16 2-term (A split).
// stage = Ah(4K)+Al(4K)+B(8K) = 16KB; 3 stages = 48KB. grid (32, 24).
// ---------------------------------------------------------------------------
#define STGQ_B 16384
#define GEMMQ_SMEM_BYTES (3 * STGQ_B)

__global__ __launch_bounds__(128, 3) void gemm_qkv_kernel(
    const float* __restrict__ bias0, const float* __restrict__ bias1,
    const float* __restrict__ bias2)
{
    extern __shared__ __half gsq[];
    const uint32_t sb = smem_to_u32(gsq);
    const int tid = threadIdx.x;
    const int wid = tid >> 5, lane = tid & 31;
    const int wn = wid;
    const int m0 = blockIdx.x * 64, n0 = blockIdx.y * 128;

    const __half* pAh = g_xh + (size_t)m0 * E_DIM;
    const __half* pAl = g_xl + (size_t)m0 * E_DIM;
    const __half* pB  = g_wt16 + (size_t)n0 * E_DIM;

    auto issue = [&](int s, int kc) {
        const int k0 = kc * 32;
        const uint32_t stb = sb + s * STGQ_B;
        #pragma unroll
        for (int i = 0; i < 2; i++) {
            int idx = tid + i * 128;
            uint32_t row = idx >> 2, q = idx & 3;
            cpasync16(stb + swz(row, q), pAh + (size_t)row * E_DIM + k0 + q * 8);
            cpasync16(stb + 4096 + swz(row, q), pAl + (size_t)row * E_DIM + k0 + q * 8);
        }
        #pragma unroll
        for (int i = 0; i < 4; i++) {
            int idx = tid + i * 128;
            uint32_t row = idx >> 2, q = idx & 3;
            cpasync16(stb + 8192 + swz(row, q), pB + (size_t)row * E_DIM + k0 + q * 8);
        }
    };

    float c[4][4][4];
    #pragma unroll
    for (int mi = 0; mi < 4; mi++)
        #pragma unroll
        for (int ni = 0; ni < 4; ni++)
            #pragma unroll
            for (int e = 0; e < 4; e++) c[mi][ni][e] = 0.f;

    const uint32_t aRow = lane & 15;
    const uint32_t aCh = lane >> 4;
    const uint32_t bGrp = lane >> 3, bRin = lane & 7;
    const uint32_t bRowBase = wn * 32 + ((bGrp >> 1) << 3) + bRin;
    const uint32_t bCh = bGrp & 1;

    issue(0, 0); CP_COMMIT();
    issue(1, 1); CP_COMMIT();

    for (int kc = 0; kc < 32; kc++) {
        const int buf = kc % 3;
        if (kc < 31) { CP_WAIT(1); } else { CP_WAIT(0); }
        __syncthreads();
        if (kc + 2 < 32) { issue((kc + 2) % 3, kc + 2); CP_COMMIT(); }

        const uint32_t saH = sb + buf * STGQ_B;
        const uint32_t saL = saH + 4096;
        const uint32_t sB  = saH + 8192;

        #pragma unroll
        for (int ks = 0; ks < 2; ks++) {
            uint32_t ah[4][4], al[4][4], bfr[4][2];
            #pragma unroll
            for (int mi = 0; mi < 4; mi++) {
                uint32_t off = swz(aRow + mi * 16, ks * 2 + aCh);
                ldsm4(ah[mi], saH + off);
                ldsm4(al[mi], saL + off);
            }
            #pragma unroll
            for (int half = 0; half < 2; half++) {
                uint32_t off = swz(bRowBase + half * 16, ks * 2 + bCh);
                ldsm4(&bfr[half * 2][0], sB + off);
            }
            #pragma unroll
            for (int mi = 0; mi < 4; mi++)
                #pragma unroll
                for (int ni = 0; ni < 4; ni++) {
                    mma16816h(c[mi][ni], ah[mi], bfr[ni]);
                    mma16816h(c[mi][ni], al[mi], bfr[ni]);
                }
        }
    }

    const int rBase = m0 + (lane >> 2);
    const int nBase = n0 + wn * 32 + (lane & 3) * 2;
    #pragma unroll
    for (int mi = 0; mi < 4; mi++) {
        #pragma unroll
        for (int ni = 0; ni < 4; ni++) {
            int n = nBase + ni * 8;
            #pragma unroll
            for (int half = 0; half < 2; half++) {
                int row = rBase + mi * 16 + half * 8;
                float v0 = c[mi][ni][half * 2 + 0];
                float v1 = c[mi][ni][half * 2 + 1];
                const int z = n >> 10;
                const float* bias = z == 0 ? bias0 : z == 1 ? bias1 : bias2;
                const int h = (n >> 6) & 15, d = n & 63, bi = n & 1023;
                size_t o = ((size_t)h * S_LEN + row) * DH + d;
                if (z == 0) {
                    float a = (v0 + __ldg(&bias[bi + 0])) * 0.125f;
                    float b = (v1 + __ldg(&bias[bi + 1])) * 0.125f;
                    splith2(a, b, g_qh + o, g_ql + o);
                } else {
                    float a = v0 + __ldg(&bias[bi + 0]);
                    float b = v1 + __ldg(&bias[bi + 1]);
                    storeh2(a, b, (z == 1 ? g_k16 : g_v16) + o);
                }
            }
        }
    }
}

// ---------------------------------------------------------------------------
// Proj GEMM: BM=64 / BN=128, 256 threads, fp16 1-term; grid (32, 8).
// stage = A(4K)+B(8K) = 12KB; 3 stages = 36KB.
// ---------------------------------------------------------------------------
#define STGP_B 12288
#define GEMMP_SMEM_BYTES (3 * STGP_B)

__global__ __launch_bounds__(256, 2) void gemm_proj_kernel(
    const float* __restrict__ bo, float* __restrict__ out)
{
    extern __shared__ __half gs2[];
    const uint32_t sb = smem_to_u32(gs2);
    const int tid = threadIdx.x;
    const int wid = tid >> 5, lane = tid & 31;
    const int wm = wid >> 2, wn = wid & 3;
    const int m0 = blockIdx.x * 64, n0 = blockIdx.y * 128;

    const __half* pA = g_ao16 + (size_t)m0 * E_DIM;
    const __half* pB = g_wot16 + (size_t)n0 * E_DIM;

    auto issue = [&](int s, int kc) {
        const int k0 = kc * 32;
        const uint32_t stb = sb + s * STGP_B;
        {
            uint32_t row = tid >> 2, q = tid & 3;
            cpasync16(stb + swz(row, q), pA + (size_t)row * E_DIM + k0 + q * 8);
        }
        #pragma unroll
        for (int i = 0; i < 2; i++) {
            int idx = tid + i * 256;
            uint32_t row = idx >> 2, q = idx & 3;
            cpasync16(stb + 4096 + swz(row, q), pB + (size_t)row * E_DIM + k0 + q * 8);
        }
    };

    float c[2][4][4];
    #pragma unroll
    for (int mi = 0; mi < 2; mi++)
        #pragma unroll
        for (int ni = 0; ni < 4; ni++)
            #pragma unroll
            for (int e = 0; e < 4; e++) c[mi][ni][e] = 0.f;

    const uint32_t aRow = wm * 32 + (lane & 15);
    const uint32_t aCh = lane >> 4;
    const uint32_t bGrp = lane >> 3, bRin = lane & 7;
    const uint32_t bRowBase = wn * 32 + ((bGrp >> 1) << 3) + bRin;
    const uint32_t bCh = bGrp & 1;

    issue(0, 0); CP_COMMIT();
    issue(1, 1); CP_COMMIT();

    for (int kc = 0; kc < 32; kc++) {
        const int buf = kc % 3;
        if (kc < 31) { CP_WAIT(1); } else { CP_WAIT(0); }
        __syncthreads();
        if (kc + 2 < 32) { issue((kc + 2) % 3, kc + 2); CP_COMMIT(); }

        const uint32_t sA = sb + buf * STGP_B;
        const uint32_t sB = sA + 4096;

        #pragma unroll
        for (int ks = 0; ks < 2; ks++) {
            uint32_t afr[2][4], bfr[4][2];
            #pragma unroll
            for (int mi = 0; mi < 2; mi++) {
                uint32_t off = swz(aRow + mi * 16, ks * 2 + aCh);
                ldsm4(afr[mi], sA + off);
            }
            #pragma unroll
            for (int half = 0; half < 2; half++) {
                uint32_t off = swz(bRowBase + half * 16, ks * 2 + bCh);
                ldsm4(&bfr[half * 2][0], sB + off);
            }
            #pragma unroll
            for (int mi = 0; mi < 2; mi++)
                #pragma unroll
                for (int ni = 0; ni < 4; ni++)
                    mma16816h(c[mi][ni], afr[mi], bfr[ni]);
        }
    }

    const int rBase = m0 + wm * 32 + (lane >> 2);
    const int nBase = n0 + wn * 32 + (lane & 3) * 2;
    #pragma unroll
    for (int mi = 0; mi < 2; mi++) {
        #pragma unroll
        for (int ni = 0; ni < 4; ni++) {
            int n = nBase + ni * 8;
            #pragma unroll
            for (int half = 0; half < 2; half++) {
                int row = rBase + mi * 16 + half * 8;
                float2 o;
                o.x = c[mi][ni][half * 2 + 0] + __ldg(&bo[n + 0]);
                o.y = c[mi][ni][half * 2 + 1] + __ldg(&bo[n + 1]);
                *(float2*)&out[(size_t)row * E_DIM + n] = o;
            }
        }
    }
}

// ---------------------------------------------------------------------------
// Split-KV tensor-core causal flash attention, fp16.
// QK^T: Q 2-term split; PV: single-fp16 P. K/V single fp16.
// ---------------------------------------------------------------------------
#define KV_TILE_B  8192
#define KV_STAGE_B 16384
#define ATN_SMEM_BYTES (2 * KV_STAGE_B)   // 32768

__global__ __launch_bounds__(128, 3) void attn_mma_kernel()
{
    extern __shared__ __half as2[];
    const uint32_t sbq = smem_to_u32(as2);
    const int tid = threadIdx.x, lane = tid & 31, w = tid >> 5;
    const int i0    = ((int)gridDim.x >> 1) - 1 - ((int)blockIdx.x >> 1);
    const int split = blockIdx.x & 1;
    const int h = blockIdx.y;

    const int total = i0 + 1;
    const int half  = (total + 1) >> 1;
    const int jb = split ? half : 0;
    const int je = split ? total : half;

    const int rowq = lane >> 2, colq = (lane & 3) * 2;
    const size_t pbase = ((size_t)(split * NH + h) * S_LEN) + i0 * 64;

    if (jb >= je) {
        const int r0 = w * 16 + rowq;
        #pragma unroll
        for (int ni = 0; ni < 8; ni++) {
            const int col = colq + ni * 8;
            float2 z2 = make_float2(0.f, 0.f);
            *(float2*)&g_opart[(pbase + r0) * DH + col] = z2;
            *(float2*)&g_opart[(pbase + r0 + 8) * DH + col] = z2;
        }
        if ((lane & 3) == 0) {
            g_mpart[pbase + r0] = -1e30f;
            g_mpart[pbase + r0 + 8] = -1e30f;
            g_lpart[pbase + r0] = 0.f;
            g_lpart[pbase + r0 + 8] = 0.f;
        }
        return;
    }

    auto load_kv = [&](int s, int jt) {
        const size_t gofs = ((size_t)h * S_LEN + jt * 64) * DH;
        const __half* srcK = g_k16 + gofs;
        const __half* srcV = g_v16 + gofs;
        const uint32_t stb = sbq + s * KV_STAGE_B;
        #pragma unroll
        for (int i = 0; i < 4; i++) {
            int idx = tid + i * 128;
            uint32_t row = idx >> 3, q = idx & 7;
            cpasync16(stb + swz8(row, q), srcK + row * 64 + q * 8);
            cpasync16(stb + KV_TILE_B + swz8(row, q), srcV + row * 64 + q * 8);
        }
    };

    load_kv(0, jb);
    CP_COMMIT();

    const __half* Qh = g_qh + ((size_t)h * S_LEN + i0 * 64) * DH;
    const __half* Ql = g_ql + ((size_t)h * S_LEN + i0 * 64) * DH;
    uint32_t aQh[4][4], aQl[4][4];
    {
        const int qr = w * 16 + rowq;
        const int qc = colq;
        #pragma unroll
        for (int ks = 0; ks < 4; ks++) {
            const __half* ph = Qh + (size_t)qr * DH + ks * 16 + qc;
            const __half* pl = Ql + (size_t)qr * DH + ks * 16 + qc;
            aQh[ks][0] = *(const uint32_t*)(ph);
            aQh[ks][1] = *(const uint32_t*)(ph + 8 * DH);
            aQh[ks][2] = *(const uint32_t*)(ph + 8);
            aQh[ks][3] = *(const uint32_t*)(ph + 8 * DH + 8);
            aQl[ks][0] = *(const uint32_t*)(pl);
            aQl[ks][1] = *(const uint32_t*)(pl + 8 * DH);
            aQl[ks][2] = *(const uint32_t*)(pl + 8);
            aQl[ks][3] = *(const uint32_t*)(pl + 8 * DH + 8);
        }
    }

    float m0 = -1e30f, m1 = -1e30f, l0 = 0.f, l1 = 0.f;
    float oc[8][4];
    #pragma unroll
    for (int ni = 0; ni < 8; ni++)
        #pragma unroll
        for (int e = 0; e < 4; e++) oc[ni][e] = 0.f;

    const int grp = lane >> 3, rin = lane & 7;

    for (int jt = jb; jt < je; jt++) {
        const int buf = (jt - jb) & 1;
        CP_WAIT(0);
        __syncthreads();
        if (jt + 1 < je) { load_kv(buf ^ 1, jt + 1); CP_COMMIT(); }

        const uint32_t stb = sbq + buf * KV_STAGE_B;
        const uint32_t sK = stb, sV = stb + KV_TILE_B;

        // ---- S = Q K^T (Q 2-term) ----
        float sc[8][4];
        #pragma unroll
        for (int ni = 0; ni < 8; ni++)
            #pragma unroll
            for (int e = 0; e < 4; e++) sc[ni][e] = 0.f;

        #pragma unroll
        for (int ks = 0; ks < 4; ks++) {
            #pragma unroll
            for (int g = 0; g < 4; g++) {
                uint32_t kfr[4];
                uint32_t off = swz8(g * 16 + ((grp >> 1) << 3) + rin,
                                    ks * 2 + (grp & 1));
                ldsm4(kfr, sK + off);
                mma16816h(sc[2 * g],     aQh[ks], kfr);
                mma16816h(sc[2 * g],     aQl[ks], kfr);
                mma16816h(sc[2 * g + 1], aQh[ks], kfr + 2);
                mma16816h(sc[2 * g + 1], aQl[ks], kfr + 2);
            }
        }

        // ---- causal mask (diagonal tile only) ----
        if (jt == i0) {
            const int rowL0 = w * 16 + rowq, rowL1 = rowL0 + 8;
            #pragma unroll
            for (int ni = 0; ni < 8; ni++) {
                int colL = ni * 8 + colq;
                if (colL     > rowL0) sc[ni][0] = -1e30f;
                if (colL + 1 > rowL0) sc[ni][1] = -1e30f;
                if (colL     > rowL1) sc[ni][2] = -1e30f;
                if (colL + 1 > rowL1) sc[ni][3] = -1e30f;
            }
        }

        // ---- online softmax ----
        float t0 = -1e30f, t1 = -1e30f;
        #pragma unroll
        for (int ni = 0; ni < 8; ni++) {
            t0 = fmaxf(t0, fmaxf(sc[ni][0], sc[ni][1]));
            t1 = fmaxf(t1, fmaxf(sc[ni][2], sc[ni][3]));
        }
        t0 = fmaxf(t0, __shfl_xor_sync(0xffffffffu, t0, 1));
        t0 = fmaxf(t0, __shfl_xor_sync(0xffffffffu, t0, 2));
        t1 = fmaxf(t1, __shfl_xor_sync(0xffffffffu, t1, 1));
        t1 = fmaxf(t1, __shfl_xor_sync(0xffffffffu, t1, 2));
        const float m0n = fmaxf(m0, t0), m1n = fmaxf(m1, t1);
        const float f0 = __expf(m0 - m0n), f1 = __expf(m1 - m1n);

        float rs0 = 0.f, rs1 = 0.f;
        #pragma unroll
        for (int ni = 0; ni < 8; ni++) {
            sc[ni][0] = __expf(sc[ni][0] - m0n); rs0 += sc[ni][0];
            sc[ni][1] = __expf(sc[ni][1] - m0n); rs0 += sc[ni][1];
            sc[ni][2] = __expf(sc[ni][2] - m1n); rs1 += sc[ni][2];
            sc[ni][3] = __expf(sc[ni][3] - m1n); rs1 += sc[ni][3];
        }
        rs0 += __shfl_xor_sync(0xffffffffu, rs0, 1);
        rs0 += __shfl_xor_sync(0xffffffffu, rs0, 2);
        rs1 += __shfl_xor_sync(0xffffffffu, rs1, 1);
        rs1 += __shfl_xor_sync(0xffffffffu, rs1, 2);
        l0 = l0 * f0 + rs0; l1 = l1 * f1 + rs1;
        m0 = m0n; m1 = m1n;
        #pragma unroll
        for (int ni = 0; ni < 8; ni++) {
            oc[ni][0] *= f0; oc[ni][1] *= f0;
            oc[ni][2] *= f1; oc[ni][3] *= f1;
        }

        // ---- pack P fragments (single fp16) ----
        uint32_t aP[4][4];
        #pragma unroll
        for (int ks = 0; ks < 4; ks++) {
            const int ta = 2 * ks, tb = 2 * ks + 1;
            aP[ks][0] = packh2(sc[ta][0], sc[ta][1]);
            aP[ks][1] = packh2(sc[ta][2], sc[ta][3]);
            aP[ks][2] = packh2(sc[tb][0], sc[tb][1]);
            aP[ks][3] = packh2(sc[tb][2], sc[tb][3]);
        }

        // ---- O += P V (single-term) ----
        #pragma unroll
        for (int ks = 0; ks < 4; ks++) {
            #pragma unroll
            for (int g = 0; g < 4; g++) {
                uint32_t vfr[4];
                uint32_t off = swz8(ks * 16 + ((grp & 1) << 3) + rin,
                                    g * 2 + (grp >> 1));
                ldsm4t(vfr, sV + off);
                mma16816h(oc[2 * g],     aP[ks], vfr);
                mma16816h(oc[2 * g + 1], aP[ks], vfr + 2);
            }
        }
    }

    const int r0 = w * 16 + rowq;
    #pragma unroll
    for (int ni = 0; ni < 8; ni++) {
        const int col = colq + ni * 8;
        *(float2*)&g_opart[(pbase + r0) * DH + col] =
            make_float2(oc[ni][0], oc[ni][1]);
        *(float2*)&g_opart[(pbase + r0 + 8) * DH + col] =
            make_float2(oc[ni][2], oc[ni][3]);
    }
    if ((lane & 3) == 0) {
        g_mpart[pbase + r0] = m0;     g_lpart[pbase + r0] = l0;
        g_mpart[pbase + r0 + 8] = m1; g_lpart[pbase + r0 + 8] = l1;
    }
}

// ---------------------------------------------------------------------------
// Combine partials -> g_ao16 (single fp16). grid = 4096 x 256.
// ---------------------------------------------------------------------------
__global__ __launch_bounds__(256) void attn_combine_kernel()
{
    const int idx = blockIdx.x * 256 + threadIdx.x;
    const int hrow = idx >> 5;
    const int d2 = (idx & 31) * 2;
    const int row = hrow & (S_LEN - 1);
    const int h = hrow >> 11;

    const float m0 = __ldg(&g_mpart[hrow]);
    const float m1 = __ldg(&g_mpart[NH * S_LEN + hrow]);
    const float l0 = __ldg(&g_lpart[hrow]);
    const float l1 = __ldg(&g_lpart[NH * S_LEN + hrow]);
    const float M = fmaxf(m0, m1);
    const float e0 = __expf(m0 - M), e1 = __expf(m1 - M);
    const float inv = 1.f / (l0 * e0 + l1 * e1);

    float2 O0 = *(const float2*)&g_opart[(size_t)hrow * DH + d2];
    float2 O1 = *(const float2*)&g_opart[(size_t)(NH * S_LEN + hrow) * DH + d2];
    float a = (O0.x * e0 + O1.x * e1) * inv;
    float b = (O0.y * e0 + O1.y * e1) * inv;

    size_t o = (size_t)row * E_DIM + h * DH + d2;
    storeh2(a, b, g_ao16 + o);
}

// ---------------------------------------------------------------------------
extern "C" void kernel_launch(void* const* d_in, const int* in_sizes, int n_in,
                              void* d_out, int out_size)
{
    const float* x  = (const float*)d_in[0];
    const float* Wq = (const float*)d_in[1];
    const float* bq = (const float*)d_in[2];
    const float* Wk = (const float*)d_in[3];
    const float* bk = (const float*)d_in[4];
    const float* Wv = (const float*)d_in[5];
    const float* bv = (const float*)d_in[6];
    const float* Wo = (const float*)d_in[7];
    const float* bo = (const float*)d_in[8];
    float* out = (float*)d_out;

    (void)in_sizes; (void)n_in; (void)out_size;

    cudaFuncSetAttribute(gemm_qkv_kernel,
                         cudaFuncAttributeMaxDynamicSharedMemorySize, GEMMQ_SMEM_BYTES);
    cudaFuncSetAttribute(gemm_proj_kernel,
                         cudaFuncAttributeMaxDynamicSharedMemorySize, GEMMP_SMEM_BYTES);
    cudaFuncSetAttribute(attn_mma_kernel,
                         cudaFuncAttributeMaxDynamicSharedMemorySize, ATN_SMEM_BYTES);

    prep_kernel<<<dim3(16, 16, 12), 256>>>(x, Wq, Wk, Wv, Wo);
    gemm_qkv_kernel<<<dim3(32, 24), 128, GEMMQ_SMEM_BYTES>>>(bq, bk, bv);
    attn_mma_kernel<<<dim3(64, NH), 128, ATN_SMEM_BYTES>>>();
    attn_combine_kernel<<<4096, 256>>>();
    gemm_proj_kernel<<<dim3(32, 8), 256, GEMMP_SMEM_BYTES>>>(bo, out);
}